// round 2
// baseline (speedup 1.0000x reference)
#include <cuda_runtime.h>
#include <math.h>

// ---- problem constants ----
#define BB    128
#define TU    256
#define TB    128
#define TP    64
#define HD    512
#define VD    3000
#define VOOVD 3400
#define PTRD  32
#define XD    2080   // E + 3H + PTR
#define G3    1536   // 3H
#define NEGV  (-1e20f)

// ---- scratch (device globals; no allocation allowed) ----
__device__ float g_p[BB * HD];
__device__ float g_score_u[BB * TU];
__device__ float g_score_b[BB * TB];
__device__ float g_score_p[BB * TP];
__device__ float g_ctx_u[BB * HD];
__device__ float g_ctx_b[BB * HD];
__device__ float g_ctx_p[BB * HD];
__device__ float g_x[BB * XD];
__device__ float g_gi[BB * G3];
__device__ float g_gh[BB * G3];
__device__ float g_hnew[BB * HD];
__device__ float g_gen[BB * VD];
__device__ float g_cpraw[BB * TB];

// =====================================================================
// Generic GEMM: C[M,N] = A[M,K] @ W[N,K]^T + bias[N], optional tanh.
// A row stride = lda, W row stride = ldw, C row stride = N.
// Requires: M % 64 == 0, K % 16 == 0, lda/ldw % 4 == 0. N guarded.
// =====================================================================
#define BM 64
#define BN 64
#define BKK 16

__global__ __launch_bounds__(256) void gemm_bias_kernel(
    const float* __restrict__ A, int lda,
    const float* __restrict__ W, int ldw,
    const float* __restrict__ bias,
    float* __restrict__ C,
    int M, int N, int K, int act)
{
    __shared__ float As[BM][BKK];
    __shared__ float Bs[BKK][BN];

    int tid = threadIdx.x;
    int tx = tid & 15, ty = tid >> 4;
    int bm = blockIdx.y * BM;
    int bn = blockIdx.x * BN;
    int lrow = tid >> 2;            // 0..63
    int lcol = (tid & 3) * 4;       // 0,4,8,12

    float acc[4][4];
#pragma unroll
    for (int i = 0; i < 4; i++)
#pragma unroll
        for (int j = 0; j < 4; j++) acc[i][j] = 0.f;

    for (int k0 = 0; k0 < K; k0 += BKK) {
        float4 av = *(const float4*)(A + (size_t)(bm + lrow) * lda + k0 + lcol);
        *(float4*)&As[lrow][lcol] = av;
        float4 bv;
        if (bn + lrow < N)
            bv = *(const float4*)(W + (size_t)(bn + lrow) * ldw + k0 + lcol);
        else
            bv = make_float4(0.f, 0.f, 0.f, 0.f);
        Bs[lcol + 0][lrow] = bv.x;
        Bs[lcol + 1][lrow] = bv.y;
        Bs[lcol + 2][lrow] = bv.z;
        Bs[lcol + 3][lrow] = bv.w;
        __syncthreads();
#pragma unroll
        for (int k = 0; k < BKK; k++) {
            float a[4], b[4];
#pragma unroll
            for (int i = 0; i < 4; i++) a[i] = As[ty * 4 + i][k];
#pragma unroll
            for (int j = 0; j < 4; j++) b[j] = Bs[k][tx * 4 + j];
#pragma unroll
            for (int i = 0; i < 4; i++)
#pragma unroll
                for (int j = 0; j < 4; j++) acc[i][j] = fmaf(a[i], b[j], acc[i][j]);
        }
        __syncthreads();
    }

#pragma unroll
    for (int i = 0; i < 4; i++) {
        int m = bm + ty * 4 + i;
#pragma unroll
        for (int j = 0; j < 4; j++) {
            int n = bn + tx * 4 + j;
            if (n < N) {
                float v = acc[i][j] + bias[n];
                if (act) v = tanhf(v);
                C[(size_t)m * N + n] = v;
            }
        }
    }
}

// =====================================================================
// Fused score kernel:
//   score[m] = sum_n vvec[b*v_stride + n] *
//              tanh(addv[b*a_stride + n] + sum_k Enc[m,k]*W[n,k])
// with b = m / T.  N = K = 512 fixed.  M % 64 == 0.
// Covers attention scores (addv=p, vvec=v_w) and cp_raw
// (addv=Wcopy_b broadcast, vvec=hnew).
// =====================================================================
__global__ __launch_bounds__(256) void score_kernel(
    const float* __restrict__ Enc,
    const float* __restrict__ W, int ldw,
    const float* __restrict__ addv, int a_stride,
    const float* __restrict__ vvec, int v_stride,
    float* __restrict__ score, int T)
{
    __shared__ float As[BM][BKK];
    __shared__ float Bs[BKK][BN];
    __shared__ float red[BM][17];

    const int K = 512, N = 512;
    int tid = threadIdx.x;
    int tx = tid & 15, ty = tid >> 4;
    int bm = blockIdx.x * BM;
    int lrow = tid >> 2;
    int lcol = (tid & 3) * 4;

    int bidx[4];
#pragma unroll
    for (int i = 0; i < 4; i++) bidx[i] = (bm + ty * 4 + i) / T;

    float rsum[4] = {0.f, 0.f, 0.f, 0.f};

    for (int n0 = 0; n0 < N; n0 += BN) {
        float acc[4][4];
#pragma unroll
        for (int i = 0; i < 4; i++)
#pragma unroll
            for (int j = 0; j < 4; j++) acc[i][j] = 0.f;

        for (int k0 = 0; k0 < K; k0 += BKK) {
            float4 av = *(const float4*)(Enc + (size_t)(bm + lrow) * K + k0 + lcol);
            *(float4*)&As[lrow][lcol] = av;
            float4 bv = *(const float4*)(W + (size_t)(n0 + lrow) * ldw + k0 + lcol);
            Bs[lcol + 0][lrow] = bv.x;
            Bs[lcol + 1][lrow] = bv.y;
            Bs[lcol + 2][lrow] = bv.z;
            Bs[lcol + 3][lrow] = bv.w;
            __syncthreads();
#pragma unroll
            for (int k = 0; k < BKK; k++) {
                float a[4], b[4];
#pragma unroll
                for (int i = 0; i < 4; i++) a[i] = As[ty * 4 + i][k];
#pragma unroll
                for (int j = 0; j < 4; j++) b[j] = Bs[k][tx * 4 + j];
#pragma unroll
                for (int i = 0; i < 4; i++)
#pragma unroll
                    for (int j = 0; j < 4; j++) acc[i][j] = fmaf(a[i], b[j], acc[i][j]);
            }
            __syncthreads();
        }
        // epilogue: tanh + weighted reduce over n
#pragma unroll
        for (int i = 0; i < 4; i++) {
            const float* ap = addv + (size_t)bidx[i] * a_stride;
            const float* vp = vvec + (size_t)bidx[i] * v_stride;
#pragma unroll
            for (int j = 0; j < 4; j++) {
                int n = n0 + tx * 4 + j;
                float t = tanhf(ap[n] + acc[i][j]);
                rsum[i] = fmaf(t, vp[n], rsum[i]);
            }
        }
    }

#pragma unroll
    for (int i = 0; i < 4; i++) red[ty * 4 + i][tx] = rsum[i];
    __syncthreads();
    if (tid < 64) {
        float s = 0.f;
#pragma unroll
        for (int x = 0; x < 16; x++) s += red[tid][x];
        score[bm + tid] = s;
    }
}

// =====================================================================
// Softmax over masked scores + context (a @ enc). One block per batch b.
// =====================================================================
__global__ __launch_bounds__(256) void softmax_ctx_kernel(
    const float* __restrict__ score, const int* __restrict__ ids,
    const float* __restrict__ enc, float* __restrict__ ctx, int T)
{
    int b = blockIdx.x;
    int tid = threadIdx.x;
    __shared__ float sa[256];
    __shared__ float rbuf[256];

    float v = -INFINITY;
    if (tid < T) {
        float s = score[b * T + tid];
        if (ids[b * T + tid] == 0) s = NEGV;
        sa[tid] = s;
        v = s;
    }
    rbuf[tid] = v;
    __syncthreads();
    for (int s = 128; s > 0; s >>= 1) {
        if (tid < s) rbuf[tid] = fmaxf(rbuf[tid], rbuf[tid + s]);
        __syncthreads();
    }
    float mx = rbuf[0];
    __syncthreads();

    float e = 0.f;
    if (tid < T) { e = expf(sa[tid] - mx); }
    rbuf[tid] = e;
    __syncthreads();
    for (int s = 128; s > 0; s >>= 1) {
        if (tid < s) rbuf[tid] += rbuf[tid + s];
        __syncthreads();
    }
    float inv = 1.0f / rbuf[0];
    __syncthreads();
    if (tid < T) sa[tid] = e * inv;
    __syncthreads();

    for (int h = tid; h < HD; h += 256) {
        float acc = 0.f;
        for (int t = 0; t < T; t++)
            acc = fmaf(sa[t], enc[((size_t)b * T + t) * HD + h], acc);
        ctx[b * HD + h] = acc;
    }
}

// =====================================================================
// Assemble GRU input x = [emb | ctx_u | ctx_b | ctx_p | db]
// =====================================================================
__global__ void assemble_x_kernel(
    const int* __restrict__ w, const float* __restrict__ emb_table,
    const float* __restrict__ db)
{
    int idx = blockIdx.x * blockDim.x + threadIdx.x;
    if (idx >= BB * XD) return;
    int b = idx / XD, c = idx % XD;
    float v;
    if (c < 512)       v = emb_table[(size_t)w[b] * 512 + c];
    else if (c < 1024) v = g_ctx_u[b * HD + c - 512];
    else if (c < 1536) v = g_ctx_b[b * HD + c - 1024];
    else if (c < 2048) v = g_ctx_p[b * HD + c - 1536];
    else               v = db[b * PTRD + (c - 2048)];
    g_x[idx] = v;
}

// =====================================================================
// GRU gate combine
// =====================================================================
__global__ void gru_gate_kernel(const float* __restrict__ h0)
{
    int idx = blockIdx.x * blockDim.x + threadIdx.x;
    if (idx >= BB * HD) return;
    int b = idx / HD, i = idx % HD;
    const float* gi = g_gi + (size_t)b * G3;
    const float* gh = g_gh + (size_t)b * G3;
    float r = 1.f / (1.f + expf(-(gi[i] + gh[i])));
    float z = 1.f / (1.f + expf(-(gi[512 + i] + gh[512 + i])));
    float n = tanhf(gi[1024 + i] + r * gh[1024 + i]);
    g_hnew[idx] = (1.f - z) * n + z * h0[idx];
}

// =====================================================================
// Final: scatter cps, log-softmax over [gen(3000) | cps(3128)],
// logaddexp merge for n<V, OOV scatter-add for n>=V. One block per b.
// =====================================================================
__global__ __launch_bounds__(256) void final_kernel(
    const int* __restrict__ bspn_ids, const int* __restrict__ nounk,
    float* __restrict__ out)
{
    int b = blockIdx.x;
    int tid = threadIdx.x;
    __shared__ float s_cps[VD + TB];   // 3128
    __shared__ float s_cpm[TB];
    __shared__ int   s_nk[TB];
    __shared__ float rbuf[256];

    for (int i = tid; i < VD + TB; i += 256) s_cps[i] = 0.f;
    if (tid < TB) {
        float c = (bspn_ids[b * TB + tid] == 0) ? NEGV : g_cpraw[b * TB + tid];
        s_cpm[tid] = c;
        s_nk[tid] = nounk[b * TB + tid];
    }
    __syncthreads();
    if (tid == 0) {   // deterministic serial scatter (128 items)
        for (int j = 0; j < TB; j++) {
            int nk = s_nk[j];
            float c = s_cpm[j];
            if (nk < VD) s_cps[nk] += c;
            else         s_cps[VD + j] = c;
        }
    }
    __syncthreads();

    const float* genb = g_gen + (size_t)b * VD;
    // max over 6128 values
    float mx = -INFINITY;
    for (int i = tid; i < VD; i += 256) mx = fmaxf(mx, genb[i]);
    for (int i = tid; i < VD + TB; i += 256) mx = fmaxf(mx, s_cps[i]);
    rbuf[tid] = mx;
    __syncthreads();
    for (int s = 128; s > 0; s >>= 1) {
        if (tid < s) rbuf[tid] = fmaxf(rbuf[tid], rbuf[tid + s]);
        __syncthreads();
    }
    mx = rbuf[0];
    __syncthreads();
    // sum exp
    float sm = 0.f;
    for (int i = tid; i < VD; i += 256) sm += expf(genb[i] - mx);
    for (int i = tid; i < VD + TB; i += 256) sm += expf(s_cps[i] - mx);
    rbuf[tid] = sm;
    __syncthreads();
    for (int s = 128; s > 0; s >>= 1) {
        if (tid < s) rbuf[tid] += rbuf[tid + s];
        __syncthreads();
    }
    float lse = mx + logf(rbuf[0]);
    __syncthreads();

    float* outb = out + (size_t)b * VOOVD;
    // n < V : logaddexp(gen, cps_low) - lse
    for (int n = tid; n < VD; n += 256) {
        float a = genb[n], c = s_cps[n];
        float m2 = fmaxf(a, c);
        outb[n] = m2 + logf(expf(a - m2) + expf(c - m2)) - lse;
    }
    // n in [V, VOOV): OOV scatter-add of exp(cp - lse)
    for (int k = tid; k < VOOVD - VD; k += 256) {
        float add = 0.f;
        int target = VD + k;
        for (int j = 0; j < TB; j++)
            if (s_nk[j] == target) add += expf(s_cpm[j] - lse);
        outb[VD + k] = (add > 0.f) ? logf(add) : NEGV;
    }
}

// =====================================================================
// Host launcher
// =====================================================================
extern "C" void kernel_launch(void* const* d_in, const int* in_sizes, int n_in,
                              void* d_out, int out_size)
{
    const int*   dec_last_w = (const int*)  d_in[0];
    const float* h0         = (const float*)d_in[1];   // (1,B,H) => B*H
    const float* usdx_h     = (const float*)d_in[2];
    const float* bspn_h     = (const float*)d_in[3];
    const float* pvaspn_h   = (const float*)d_in[4];
    const float* db         = (const float*)d_in[5];
    const int*   usdx_ids   = (const int*)  d_in[6];
    const int*   bspn_ids   = (const int*)  d_in[7];
    const int*   pvaspn_ids = (const int*)  d_in[8];
    const int*   bspn_nounk = (const int*)  d_in[9];
    // d_in[10] bspn_onehot: unused (reconstructed from nounk)
    const float* emb_table  = (const float*)d_in[11];
    const float* attn_W     = (const float*)d_in[12];
    const float* attn_b     = (const float*)d_in[13];
    const float* v_w        = (const float*)d_in[14];
    const float* Wcopy_w    = (const float*)d_in[15];
    const float* Wcopy_b    = (const float*)d_in[16];
    const float* Wgen_w     = (const float*)d_in[17];
    const float* Wgen_b     = (const float*)d_in[18];
    const float* gru_W_ih   = (const float*)d_in[19];
    const float* gru_W_hh   = (const float*)d_in[20];
    const float* gru_b_ih   = (const float*)d_in[21];
    const float* gru_b_hh   = (const float*)d_in[22];
    float* out = (float*)d_out;

    float *p_, *su_, *sb_, *sp_, *cu_, *cb_, *cp_, *x_, *gi_, *gh_, *hn_, *gen_;
    cudaGetSymbolAddress((void**)&p_,   g_p);
    cudaGetSymbolAddress((void**)&su_,  g_score_u);
    cudaGetSymbolAddress((void**)&sb_,  g_score_b);
    cudaGetSymbolAddress((void**)&sp_,  g_score_p);
    cudaGetSymbolAddress((void**)&cu_,  g_ctx_u);
    cudaGetSymbolAddress((void**)&cb_,  g_ctx_b);
    cudaGetSymbolAddress((void**)&cp_,  g_ctx_p);
    cudaGetSymbolAddress((void**)&x_,   g_x);
    cudaGetSymbolAddress((void**)&gi_,  g_gi);
    cudaGetSymbolAddress((void**)&gh_,  g_gh);
    cudaGetSymbolAddress((void**)&hn_,  g_hnew);
    cudaGetSymbolAddress((void**)&gen_, g_gen);
    float* cpraw_;
    cudaGetSymbolAddress((void**)&cpraw_, g_cpraw);

    // 1) p = h0 @ W1^T + attn_b   (W1 = attn_W[:, :H], ldw = 2H)
    gemm_bias_kernel<<<dim3(HD / BN, BB / BM), 256>>>(
        h0, HD, attn_W, 2 * HD, attn_b, p_, BB, HD, HD, 0);

    // 2) attention scores (W2 = attn_W[:, H:], ldw = 2H)
    score_kernel<<<BB * TU / BM, 256>>>(usdx_h,   attn_W + HD, 2 * HD, p_, HD, v_w, 0, su_, TU);
    score_kernel<<<BB * TB / BM, 256>>>(bspn_h,   attn_W + HD, 2 * HD, p_, HD, v_w, 0, sb_, TB);
    score_kernel<<<BB * TP / BM, 256>>>(pvaspn_h, attn_W + HD, 2 * HD, p_, HD, v_w, 0, sp_, TP);

    // 3) masked softmax + context
    softmax_ctx_kernel<<<BB, 256>>>(su_, usdx_ids,   usdx_h,   cu_, TU);
    softmax_ctx_kernel<<<BB, 256>>>(sb_, bspn_ids,   bspn_h,   cb_, TB);
    softmax_ctx_kernel<<<BB, 256>>>(sp_, pvaspn_ids, pvaspn_h, cp_, TP);

    // 4) GRU
    assemble_x_kernel<<<(BB * XD + 255) / 256, 256>>>(dec_last_w, emb_table, db);
    gemm_bias_kernel<<<dim3(G3 / BN, BB / BM), 256>>>(
        x_, XD, gru_W_ih, XD, gru_b_ih, gi_, BB, G3, XD, 0);
    gemm_bias_kernel<<<dim3(G3 / BN, BB / BM), 256>>>(
        h0, HD, gru_W_hh, HD, gru_b_hh, gh_, BB, G3, HD, 0);
    gru_gate_kernel<<<(BB * HD + 255) / 256, 256>>>(h0);

    // 5) gen logits
    gemm_bias_kernel<<<dim3((VD + BN - 1) / BN, BB / BM), 256>>>(
        hn_, HD, Wgen_w, HD, Wgen_b, gen_, BB, VD, HD, 0);

    // 6) cp_raw[b,t] = hnew[b] . tanh(Wcopy_b + Wcopy_w @ bspn_h[b,t])
    score_kernel<<<BB * TB / BM, 256>>>(bspn_h, Wcopy_w, HD, Wcopy_b, 0, hn_, HD, cpraw_, TB);

    // 7) final scatter + log-softmax + merge
    final_kernel<<<BB, 256>>>(bspn_ids, bspn_nounk, out);
}

// round 4
// speedup vs baseline: 2.1349x; 2.1349x over previous
#include <cuda_runtime.h>
#include <cuda_bf16.h>
#include <math.h>
#include <stdint.h>

// ---- problem constants ----
#define BB    128
#define TU    256
#define TB    128
#define TP    64
#define HD    512
#define VD    3000
#define VOOVD 3400
#define PTRD  32
#define XD    2080   // E + 3H + PTR
#define G3    1536   // 3H
#define NEGV  (-1e20f)

// ---- scratch (device globals; no allocation allowed) ----
__device__ float g_p[BB * HD];
__device__ float g_score_u[BB * TU];
__device__ float g_score_b[BB * TB];
__device__ float g_score_p[BB * TP];
__device__ float g_ctx_u[BB * HD];
__device__ float g_ctx_b[BB * HD];
__device__ float g_ctx_p[BB * HD];
__device__ float g_x[BB * XD];
__device__ float g_gi[BB * G3];
__device__ float g_gh[BB * G3];
__device__ float g_hnew[BB * HD];
__device__ float g_gen[BB * VD];
__device__ float g_cpraw[BB * TB];

// =====================================================================
// tf32 helpers (sm_80+ PTX; compiles at plain compute_103)
// =====================================================================
__device__ __forceinline__ float to_tf32(float x) {
    float y;
    asm("cvt.rna.tf32.f32 %0, %1;" : "=f"(y) : "f"(x));
    return y;
}
__device__ __forceinline__ void mma_tf32(float* d,
    uint32_t a0, uint32_t a1, uint32_t a2, uint32_t a3,
    uint32_t b0, uint32_t b1)
{
    asm volatile(
        "mma.sync.aligned.m16n8k8.row.col.f32.tf32.tf32.f32 "
        "{%0,%1,%2,%3}, {%4,%5,%6,%7}, {%8,%9}, {%0,%1,%2,%3};"
        : "+f"(d[0]), "+f"(d[1]), "+f"(d[2]), "+f"(d[3])
        : "r"(a0), "r"(a1), "r"(a2), "r"(a3), "r"(b0), "r"(b1));
}

// =====================================================================
// tf32 tensor-core score kernel:
//   score[m] = sum_n vvec[b,n] * tanh(addv[b,n] + sum_k Enc[m,k]*W[n,k])
// with b = m / T (constant per block since BM=64 <= T for all T used).
// BM=64 rows; A resident in smem (tf32) for whole K=512; N done in two
// 256-wide passes; B streamed per 64-K-chunk from L2.
// Conflict-free smem: A stride 516 f32, B stride 68 f32 (4r+t banks).
// =====================================================================
#define AS_F   (64 * 516)                 // 33024 floats
#define BS_F   (256 * 68)                 // 17408 floats
#define SP_OFF (AS_F + BS_F)              // 50432
#define SV_OFF (SP_OFF + 512)
#define RED_OFF (SV_OFF + 512)            // 51456
#define SMEM_F (RED_OFF + 64 * 33)        // 53568 floats
#define SMEM_SZ (SMEM_F * 4)              // 214272 bytes

__global__ __launch_bounds__(256) void score_tf32_kernel(
    const float* __restrict__ Enc,
    const float* __restrict__ W, int ldw,
    const float* __restrict__ addv, int a_stride,
    const float* __restrict__ vvec, int v_stride,
    float* __restrict__ score, int T)
{
    extern __shared__ float sm[];
    float* As  = sm;
    float* Bs  = sm + AS_F;
    float* sp  = sm + SP_OFF;
    float* sv  = sm + SV_OFF;
    float* red = sm + RED_OFF;

    int tid = threadIdx.x;
    int wid = tid >> 5, lane = tid & 31;
    int gr = lane >> 2, tg = lane & 3;
    int bm = blockIdx.x * 64;
    int b = bm / T;

    // preload addv / vvec rows for this batch
    for (int i = tid; i < 512; i += 256) {
        sp[i] = addv[(size_t)b * a_stride + i];
        sv[i] = vvec[(size_t)b * v_stride + i];
    }
    // A fill: 64 x 512, cvt to tf32, stride 516
    for (int idx = tid; idx < 8192; idx += 256) {
        int r = idx >> 7, cq = (idx & 127) << 2;
        float4 v = *(const float4*)(Enc + (size_t)(bm + r) * 512 + cq);
        float4 o;
        o.x = to_tf32(v.x); o.y = to_tf32(v.y);
        o.z = to_tf32(v.z); o.w = to_tf32(v.w);
        *(float4*)(As + r * 516 + cq) = o;
    }
    __syncthreads();

    int r0w = (wid & 1) * 32;       // warp m offset within 64
    int n0w = (wid >> 1) * 64;      // warp n offset within 256

    const uint32_t* Asu = (const uint32_t*)As;
    const uint32_t* Bsu = (const uint32_t*)Bs;

    for (int ni = 0; ni < 2; ni++) {
        float acc[2][8][4];
#pragma unroll
        for (int mt = 0; mt < 2; mt++)
#pragma unroll
            for (int nt = 0; nt < 8; nt++)
#pragma unroll
                for (int q = 0; q < 4; q++) acc[mt][nt][q] = 0.f;

        for (int kc = 0; kc < 8; kc++) {
            __syncthreads();
            // B fill: 256 n-rows x 64 k, cvt tf32, stride 68
            const float* Wsrc = W + (size_t)(ni * 256) * ldw + kc * 64;
            for (int idx = tid; idx < 4096; idx += 256) {
                int r = idx >> 4, cq = (idx & 15) << 2;
                float4 v = *(const float4*)(Wsrc + (size_t)r * ldw + cq);
                float4 o;
                o.x = to_tf32(v.x); o.y = to_tf32(v.y);
                o.z = to_tf32(v.z); o.w = to_tf32(v.w);
                *(float4*)(Bs + r * 68 + cq) = o;
            }
            __syncthreads();

#pragma unroll
            for (int kk = 0; kk < 8; kk++) {
                int kb = kk * 8 + tg;
                uint32_t bf[8][2];
#pragma unroll
                for (int nt = 0; nt < 8; nt++) {
                    int bn = n0w + nt * 8 + gr;
                    bf[nt][0] = Bsu[bn * 68 + kb];
                    bf[nt][1] = Bsu[bn * 68 + kb + 4];
                }
#pragma unroll
                for (int mt = 0; mt < 2; mt++) {
                    int ar = r0w + mt * 16 + gr;
                    int ak = kc * 64 + kb;
                    uint32_t a0 = Asu[ar * 516 + ak];
                    uint32_t a1 = Asu[(ar + 8) * 516 + ak];
                    uint32_t a2 = Asu[ar * 516 + ak + 4];
                    uint32_t a3 = Asu[(ar + 8) * 516 + ak + 4];
#pragma unroll
                    for (int nt = 0; nt < 8; nt++)
                        mma_tf32(acc[mt][nt], a0, a1, a2, a3, bf[nt][0], bf[nt][1]);
                }
            }
        }

        // epilogue for this n-half: tanh + weighted reduce
#pragma unroll
        for (int mt = 0; mt < 2; mt++) {
            float p0 = 0.f, p1 = 0.f;
#pragma unroll
            for (int nt = 0; nt < 8; nt++) {
                int nc = ni * 256 + n0w + nt * 8 + tg * 2;
                p0 = fmaf(tanhf(sp[nc]     + acc[mt][nt][0]), sv[nc],     p0);
                p0 = fmaf(tanhf(sp[nc + 1] + acc[mt][nt][1]), sv[nc + 1], p0);
                p1 = fmaf(tanhf(sp[nc]     + acc[mt][nt][2]), sv[nc],     p1);
                p1 = fmaf(tanhf(sp[nc + 1] + acc[mt][nt][3]), sv[nc + 1], p1);
            }
            int slot = tg + 4 * (wid >> 1) + 16 * ni;
            int row0 = r0w + mt * 16 + gr;
            if (ni == 0) {
                red[row0 * 33 + slot] = p0;
                red[(row0 + 8) * 33 + slot] = p1;
            } else {
                red[row0 * 33 + slot] += p0;
                red[(row0 + 8) * 33 + slot] += p1;
            }
        }
    }
    __syncthreads();
    if (tid < 64) {
        float s = 0.f;
#pragma unroll
        for (int j = 0; j < 32; j++) s += red[tid * 33 + j];
        score[bm + tid] = s;
    }
}

// =====================================================================
// Generic SIMT GEMM: C[M,N] = A[M,K] @ W[N,K]^T + bias[N].
// =====================================================================
#define BM 64
#define BN 64
#define BKK 16

__global__ __launch_bounds__(256) void gemm_bias_kernel(
    const float* __restrict__ A, int lda,
    const float* __restrict__ W, int ldw,
    const float* __restrict__ bias,
    float* __restrict__ C,
    int M, int N, int K)
{
    __shared__ float As[BM][BKK];
    __shared__ float Bs[BKK][BN];

    int tid = threadIdx.x;
    int tx = tid & 15, ty = tid >> 4;
    int bm = blockIdx.y * BM;
    int bn = blockIdx.x * BN;
    int lrow = tid >> 2;
    int lcol = (tid & 3) * 4;

    float acc[4][4];
#pragma unroll
    for (int i = 0; i < 4; i++)
#pragma unroll
        for (int j = 0; j < 4; j++) acc[i][j] = 0.f;

    for (int k0 = 0; k0 < K; k0 += BKK) {
        float4 av = *(const float4*)(A + (size_t)(bm + lrow) * lda + k0 + lcol);
        *(float4*)&As[lrow][lcol] = av;
        float4 bv;
        if (bn + lrow < N)
            bv = *(const float4*)(W + (size_t)(bn + lrow) * ldw + k0 + lcol);
        else
            bv = make_float4(0.f, 0.f, 0.f, 0.f);
        Bs[lcol + 0][lrow] = bv.x;
        Bs[lcol + 1][lrow] = bv.y;
        Bs[lcol + 2][lrow] = bv.z;
        Bs[lcol + 3][lrow] = bv.w;
        __syncthreads();
#pragma unroll
        for (int k = 0; k < BKK; k++) {
            float a[4], bq[4];
#pragma unroll
            for (int i = 0; i < 4; i++) a[i] = As[ty * 4 + i][k];
#pragma unroll
            for (int j = 0; j < 4; j++) bq[j] = Bs[k][tx * 4 + j];
#pragma unroll
            for (int i = 0; i < 4; i++)
#pragma unroll
                for (int j = 0; j < 4; j++) acc[i][j] = fmaf(a[i], bq[j], acc[i][j]);
        }
        __syncthreads();
    }

#pragma unroll
    for (int i = 0; i < 4; i++) {
        int m = bm + ty * 4 + i;
#pragma unroll
        for (int j = 0; j < 4; j++) {
            int n = bn + tx * 4 + j;
            if (n < N)
                C[(size_t)m * N + n] = acc[i][j] + bias[n];
        }
    }
}

// =====================================================================
// Softmax over masked scores + context. One block per batch b.
// =====================================================================
__global__ __launch_bounds__(256) void softmax_ctx_kernel(
    const float* __restrict__ score, const int* __restrict__ ids,
    const float* __restrict__ enc, float* __restrict__ ctx, int T)
{
    int b = blockIdx.x;
    int tid = threadIdx.x;
    __shared__ float sa[256];
    __shared__ float rbuf[256];

    float v = -INFINITY;
    if (tid < T) {
        float s = score[b * T + tid];
        if (ids[b * T + tid] == 0) s = NEGV;
        sa[tid] = s;
        v = s;
    }
    rbuf[tid] = v;
    __syncthreads();
    for (int s = 128; s > 0; s >>= 1) {
        if (tid < s) rbuf[tid] = fmaxf(rbuf[tid], rbuf[tid + s]);
        __syncthreads();
    }
    float mx = rbuf[0];
    __syncthreads();

    float e = 0.f;
    if (tid < T) e = expf(sa[tid] - mx);
    rbuf[tid] = e;
    __syncthreads();
    for (int s = 128; s > 0; s >>= 1) {
        if (tid < s) rbuf[tid] += rbuf[tid + s];
        __syncthreads();
    }
    float inv = 1.0f / rbuf[0];
    __syncthreads();
    if (tid < T) sa[tid] = e * inv;
    __syncthreads();

    for (int h = tid; h < HD; h += 256) {
        float acc = 0.f;
        for (int t = 0; t < T; t++)
            acc = fmaf(sa[t], enc[((size_t)b * T + t) * HD + h], acc);
        ctx[b * HD + h] = acc;
    }
}

// =====================================================================
// Assemble GRU input x = [emb | ctx_u | ctx_b | ctx_p | db]
// =====================================================================
__global__ void assemble_x_kernel(
    const int* __restrict__ w, const float* __restrict__ emb_table,
    const float* __restrict__ db)
{
    int idx = blockIdx.x * blockDim.x + threadIdx.x;
    if (idx >= BB * XD) return;
    int b = idx / XD, c = idx % XD;
    float v;
    if (c < 512)       v = emb_table[(size_t)w[b] * 512 + c];
    else if (c < 1024) v = g_ctx_u[b * HD + c - 512];
    else if (c < 1536) v = g_ctx_b[b * HD + c - 1024];
    else if (c < 2048) v = g_ctx_p[b * HD + c - 1536];
    else               v = db[b * PTRD + (c - 2048)];
    g_x[idx] = v;
}

// =====================================================================
// GRU gate combine
// =====================================================================
__global__ void gru_gate_kernel(const float* __restrict__ h0)
{
    int idx = blockIdx.x * blockDim.x + threadIdx.x;
    if (idx >= BB * HD) return;
    int b = idx / HD, i = idx % HD;
    const float* gi = g_gi + (size_t)b * G3;
    const float* gh = g_gh + (size_t)b * G3;
    float r = 1.f / (1.f + expf(-(gi[i] + gh[i])));
    float z = 1.f / (1.f + expf(-(gi[512 + i] + gh[512 + i])));
    float n = tanhf(gi[1024 + i] + r * gh[1024 + i]);
    g_hnew[idx] = (1.f - z) * n + z * h0[idx];
}

// =====================================================================
// Final: scatter cps, log-softmax over [gen | cps], merge + OOV.
// =====================================================================
__global__ __launch_bounds__(256) void final_kernel(
    const int* __restrict__ bspn_ids, const int* __restrict__ nounk,
    float* __restrict__ out)
{
    int b = blockIdx.x;
    int tid = threadIdx.x;
    __shared__ float s_cps[VD + TB];
    __shared__ float s_cpm[TB];
    __shared__ int   s_nk[TB];
    __shared__ float rbuf[256];

    for (int i = tid; i < VD + TB; i += 256) s_cps[i] = 0.f;
    if (tid < TB) {
        float c = g_cpraw[b * TB + tid];
        if (bspn_ids[b * TB + tid] == 0) c = NEGV;
        s_cpm[tid] = c;
        s_nk[tid] = nounk[b * TB + tid];
    }
    __syncthreads();
    if (tid == 0) {
        for (int j = 0; j < TB; j++) {
            int nk = s_nk[j];
            float c = s_cpm[j];
            if (nk < VD) s_cps[nk] += c;
            else         s_cps[VD + j] = c;
        }
    }
    __syncthreads();

    const float* genb = g_gen + (size_t)b * VD;
    float mx = -INFINITY;
    for (int i = tid; i < VD; i += 256) mx = fmaxf(mx, genb[i]);
    for (int i = tid; i < VD + TB; i += 256) mx = fmaxf(mx, s_cps[i]);
    rbuf[tid] = mx;
    __syncthreads();
    for (int s = 128; s > 0; s >>= 1) {
        if (tid < s) rbuf[tid] = fmaxf(rbuf[tid], rbuf[tid + s]);
        __syncthreads();
    }
    mx = rbuf[0];
    __syncthreads();
    float sm = 0.f;
    for (int i = tid; i < VD; i += 256) sm += expf(genb[i] - mx);
    for (int i = tid; i < VD + TB; i += 256) sm += expf(s_cps[i] - mx);
    rbuf[tid] = sm;
    __syncthreads();
    for (int s = 128; s > 0; s >>= 1) {
        if (tid < s) rbuf[tid] += rbuf[tid + s];
        __syncthreads();
    }
    float lse = mx + logf(rbuf[0]);
    __syncthreads();

    float* outb = out + (size_t)b * VOOVD;
    for (int n = tid; n < VD; n += 256) {
        float a = genb[n], c = s_cps[n];
        float m2 = fmaxf(a, c);
        outb[n] = m2 + logf(expf(a - m2) + expf(c - m2)) - lse;
    }
    for (int k = tid; k < VOOVD - VD; k += 256) {
        float add = 0.f;
        int target = VD + k;
        for (int j = 0; j < TB; j++)
            if (s_nk[j] == target) add += expf(s_cpm[j] - lse);
        outb[VD + k] = (add > 0.f) ? logf(add) : NEGV;
    }
}

// =====================================================================
// Host launcher
// =====================================================================
extern "C" void kernel_launch(void* const* d_in, const int* in_sizes, int n_in,
                              void* d_out, int out_size)
{
    const int*   dec_last_w = (const int*)  d_in[0];
    const float* h0         = (const float*)d_in[1];
    const float* usdx_h     = (const float*)d_in[2];
    const float* bspn_h     = (const float*)d_in[3];
    const float* pvaspn_h   = (const float*)d_in[4];
    const float* db         = (const float*)d_in[5];
    const int*   usdx_ids   = (const int*)  d_in[6];
    const int*   bspn_ids   = (const int*)  d_in[7];
    const int*   pvaspn_ids = (const int*)  d_in[8];
    const int*   bspn_nounk = (const int*)  d_in[9];
    const float* emb_table  = (const float*)d_in[11];
    const float* attn_W     = (const float*)d_in[12];
    const float* attn_b     = (const float*)d_in[13];
    const float* v_w        = (const float*)d_in[14];
    const float* Wcopy_w    = (const float*)d_in[15];
    const float* Wcopy_b    = (const float*)d_in[16];
    const float* Wgen_w     = (const float*)d_in[17];
    const float* Wgen_b     = (const float*)d_in[18];
    const float* gru_W_ih   = (const float*)d_in[19];
    const float* gru_W_hh   = (const float*)d_in[20];
    const float* gru_b_ih   = (const float*)d_in[21];
    const float* gru_b_hh   = (const float*)d_in[22];
    float* out = (float*)d_out;

    float *p_, *su_, *sb_, *sp_, *cu_, *cb_, *cp_, *x_, *gi_, *gh_, *hn_, *gen_, *cpraw_;
    cudaGetSymbolAddress((void**)&p_,     g_p);
    cudaGetSymbolAddress((void**)&su_,    g_score_u);
    cudaGetSymbolAddress((void**)&sb_,    g_score_b);
    cudaGetSymbolAddress((void**)&sp_,    g_score_p);
    cudaGetSymbolAddress((void**)&cu_,    g_ctx_u);
    cudaGetSymbolAddress((void**)&cb_,    g_ctx_b);
    cudaGetSymbolAddress((void**)&cp_,    g_ctx_p);
    cudaGetSymbolAddress((void**)&x_,     g_x);
    cudaGetSymbolAddress((void**)&gi_,    g_gi);
    cudaGetSymbolAddress((void**)&gh_,    g_gh);
    cudaGetSymbolAddress((void**)&hn_,    g_hnew);
    cudaGetSymbolAddress((void**)&gen_,   g_gen);
    cudaGetSymbolAddress((void**)&cpraw_, g_cpraw);

    cudaFuncSetAttribute(score_tf32_kernel,
                         cudaFuncAttributeMaxDynamicSharedMemorySize, SMEM_SZ);

    // 1) p = h0 @ W1^T + attn_b   (W1 = attn_W[:, :H], ldw = 2H)
    gemm_bias_kernel<<<dim3(HD / BN, BB / BM), 256>>>(
        h0, HD, attn_W, 2 * HD, attn_b, p_, BB, HD, HD);

    // 2) attention scores on tensor cores (tf32 mma.sync)
    score_tf32_kernel<<<BB * TU / 64, 256, SMEM_SZ>>>(
        usdx_h, attn_W + HD, 2 * HD, p_, HD, v_w, 0, su_, TU);
    score_tf32_kernel<<<BB * TB / 64, 256, SMEM_SZ>>>(
        bspn_h, attn_W + HD, 2 * HD, p_, HD, v_w, 0, sb_, TB);
    score_tf32_kernel<<<BB * TP / 64, 256, SMEM_SZ>>>(
        pvaspn_h, attn_W + HD, 2 * HD, p_, HD, v_w, 0, sp_, TP);

    // 3) masked softmax + context
    softmax_ctx_kernel<<<BB, 256>>>(su_, usdx_ids,   usdx_h,   cu_, TU);
    softmax_ctx_kernel<<<BB, 256>>>(sb_, bspn_ids,   bspn_h,   cb_, TB);
    softmax_ctx_kernel<<<BB, 256>>>(sp_, pvaspn_ids, pvaspn_h, cp_, TP);

    // 4) GRU
    assemble_x_kernel<<<(BB * XD + 255) / 256, 256>>>(dec_last_w, emb_table, db);
    gemm_bias_kernel<<<dim3(G3 / BN, BB / BM), 256>>>(
        x_, XD, gru_W_ih, XD, gru_b_ih, gi_, BB, G3, XD);
    gemm_bias_kernel<<<dim3(G3 / BN, BB / BM), 256>>>(
        h0, HD, gru_W_hh, HD, gru_b_hh, gh_, BB, G3, HD);
    gru_gate_kernel<<<(BB * HD + 255) / 256, 256>>>(h0);

    // 5) gen logits
    gemm_bias_kernel<<<dim3((VD + BN - 1) / BN, BB / BM), 256>>>(
        hn_, HD, Wgen_w, HD, Wgen_b, gen_, BB, VD, HD);

    // 6) cp_raw[b,t] = hnew[b] . tanh(Wcopy_b + Wcopy_w @ bspn_h[b,t])
    score_tf32_kernel<<<BB * TB / 64, 256, SMEM_SZ>>>(
        bspn_h, Wcopy_w, HD, Wcopy_b, 0, hn_, HD, cpraw_, TB);

    // 7) final scatter + log-softmax + merge
    final_kernel<<<BB, 256>>>(bspn_ids, bspn_nounk, out);
}

// round 5
// speedup vs baseline: 2.6327x; 1.2332x over previous
#include <cuda_runtime.h>
#include <cuda_bf16.h>
#include <math.h>
#include <stdint.h>

// ---- problem constants ----
#define BB    128
#define TU    256
#define TB    128
#define TP    64
#define HD    512
#define VD    3000
#define VOOVD 3400
#define PTRD  32
#define XD    2080   // E + 3H + PTR
#define G3    1536   // 3H
#define NEGV  (-1e20f)

// ---- scratch (device globals; no allocation allowed) ----
__device__ float g_p[BB * HD];
__device__ float g_score_u[BB * TU];
__device__ float g_score_b[BB * TB];
__device__ float g_score_p[BB * TP];
__device__ float g_ctx_u[BB * HD];
__device__ float g_ctx_b[BB * HD];
__device__ float g_ctx_p[BB * HD];
__device__ float g_x[BB * XD];
__device__ float g_gi[BB * G3];
__device__ float g_gh[BB * G3];
__device__ float g_hnew[BB * HD];
__device__ float g_gen[BB * VD];
__device__ float g_cpraw[BB * TB];

// =====================================================================
// mma / async-copy helpers (sm_80+ PTX; compiles at plain compute_103)
// =====================================================================
__device__ __forceinline__ void mma_tf32(float* d,
    uint32_t a0, uint32_t a1, uint32_t a2, uint32_t a3,
    uint32_t b0, uint32_t b1)
{
    asm volatile(
        "mma.sync.aligned.m16n8k8.row.col.f32.tf32.tf32.f32 "
        "{%0,%1,%2,%3}, {%4,%5,%6,%7}, {%8,%9}, {%0,%1,%2,%3};"
        : "+f"(d[0]), "+f"(d[1]), "+f"(d[2]), "+f"(d[3])
        : "r"(a0), "r"(a1), "r"(a2), "r"(a3), "r"(b0), "r"(b1));
}
__device__ __forceinline__ void cpa8(uint32_t s, const void* g) {
    asm volatile("cp.async.ca.shared.global [%0], [%1], 8;" :: "r"(s), "l"(g));
}
__device__ __forceinline__ void cpa_commit() {
    asm volatile("cp.async.commit_group;");
}
__device__ __forceinline__ void cpa_wait1() {
    asm volatile("cp.async.wait_group 1;");
}
__device__ __forceinline__ float tanh_fast(float x) {
    float y; asm("tanh.approx.f32 %0, %1;" : "=f"(y) : "f"(x)); return y;
}

// =====================================================================
// tf32 tensor-core score kernel (pipelined, BM=128):
//   score[m] = sum_n vvec[b,n] * tanh(addv[b,n] + sum_k Enc[m,k]*W[n,k])
// Block: 128 M-rows x full N=512 (two 256-wide passes), K=512 in 8
// chunks of 64 per pass. A & B chunks double-buffered via cp.async.
// Raw f32 bits fed to tf32 mma (HW truncation). Stride 68 => 4r+t bank
// pattern, conflict-free for all frag loads; 8B-aligned rows for cp.async.
// =====================================================================
#define SC_STR 68
#define A_BUF_F (128 * SC_STR)        // 8704 floats per buffer
#define B_BUF_F (256 * SC_STR)        // 17408 floats per buffer
#define AS_OFF 0
#define BS_OFF (2 * A_BUF_F)          // 17408
#define SP_OFF (BS_OFF + 2 * B_BUF_F) // 52224
#define SV_OFF (SP_OFF + 1024)
#define RED_OFF (SV_OFF + 1024)       // 54272
#define SMEM_F (RED_OFF + 128 * 17)   // 56448
#define SMEM_SZ (SMEM_F * 4)          // 225792 bytes

__device__ __forceinline__ void sc_prefetch(
    const float* __restrict__ Enc, const float* __restrict__ W, int ldw,
    int bm, int kc, int ni, int bb, uint32_t smb, int tid)
{
    // A chunk: 128 rows x 64 k  (one warp fills one 256B row per iter)
    const float* Asrc = Enc + (size_t)bm * 512 + kc * 64;
    uint32_t adst = smb + (AS_OFF + bb * A_BUF_F) * 4;
    #pragma unroll
    for (int it = 0; it < 16; it++) {
        int idx = tid + it * 256;
        int row = idx >> 5, kd = (idx & 31) * 2;
        cpa8(adst + (row * SC_STR + kd) * 4, Asrc + (size_t)row * 512 + kd);
    }
    // B chunk: 256 n-rows x 64 k
    const float* Bsrc = W + (size_t)(ni * 256) * ldw + kc * 64;
    uint32_t bdst = smb + (BS_OFF + bb * B_BUF_F) * 4;
    #pragma unroll
    for (int it = 0; it < 32; it++) {
        int idx = tid + it * 256;
        int row = idx >> 5, kd = (idx & 31) * 2;
        cpa8(bdst + (row * SC_STR + kd) * 4, Bsrc + (size_t)row * ldw + kd);
    }
    cpa_commit();
}

__global__ __launch_bounds__(256, 1) void score_tf32_kernel(
    const float* __restrict__ Enc,
    const float* __restrict__ W, int ldw,
    const float* __restrict__ addv, int a_stride,
    const float* __restrict__ vvec, int v_stride,
    float* __restrict__ score, int T)
{
    extern __shared__ float sm[];
    uint32_t smb = (uint32_t)__cvta_generic_to_shared(sm);
    int tid = threadIdx.x;
    int wid = tid >> 5, lane = tid & 31;
    int gr = lane >> 2, tg = lane & 3;
    int bm = blockIdx.x * 128;
    int bA = bm / T;

    int m0 = (wid & 1) * 64;       // warp m offset (2 m-warps)
    int n0 = (wid >> 1) * 64;      // warp n offset within 256 (4 n-warps)

    // preload addv/vvec for the (up to 2) batch rows this block spans
    for (int i = tid; i < 1024; i += 256) {
        int sl = i >> 9, n = i & 511;
        int bs = (bm + sl * 64) / T;
        sm[SP_OFF + i] = addv[(size_t)bs * a_stride + n];
        sm[SV_OFF + i] = vvec[(size_t)bs * v_stride + n];
    }

    sc_prefetch(Enc, W, ldw, bm, 0, 0, 0, smb, tid);
    sc_prefetch(Enc, W, ldw, bm, 1, 0, 1, smb, tid);

    float acc[4][8][4];

    for (int ph = 0; ph < 16; ph++) {
        int ni = ph >> 3, kc = ph & 7, bb = ph & 1;
        if (kc == 0) {
            #pragma unroll
            for (int mt = 0; mt < 4; mt++)
                #pragma unroll
                for (int nt = 0; nt < 8; nt++)
                    #pragma unroll
                    for (int q = 0; q < 4; q++) acc[mt][nt][q] = 0.f;
        }
        cpa_wait1();
        __syncthreads();

        const uint32_t* Au = (const uint32_t*)(sm + AS_OFF + bb * A_BUF_F);
        const uint32_t* Bu = (const uint32_t*)(sm + BS_OFF + bb * B_BUF_F);
        #pragma unroll
        for (int kk = 0; kk < 8; kk++) {
            int kb = kk * 8 + tg;
            uint32_t bf[8][2];
            #pragma unroll
            for (int nt = 0; nt < 8; nt++) {
                int bn = n0 + nt * 8 + gr;
                bf[nt][0] = Bu[bn * SC_STR + kb];
                bf[nt][1] = Bu[bn * SC_STR + kb + 4];
            }
            #pragma unroll
            for (int mt = 0; mt < 4; mt++) {
                int ar = m0 + mt * 16 + gr;
                uint32_t a0 = Au[ar * SC_STR + kb];
                uint32_t a1 = Au[(ar + 8) * SC_STR + kb];
                uint32_t a2 = Au[ar * SC_STR + kb + 4];
                uint32_t a3 = Au[(ar + 8) * SC_STR + kb + 4];
                #pragma unroll
                for (int nt = 0; nt < 8; nt++)
                    mma_tf32(acc[mt][nt], a0, a1, a2, a3, bf[nt][0], bf[nt][1]);
            }
        }
        __syncthreads();

        int ph2 = ph + 2;
        if (ph2 < 16)
            sc_prefetch(Enc, W, ldw, bm, ph2 & 7, ph2 >> 3, bb, smb, tid);
        else
            cpa_commit();   // empty group keeps wait_group accounting aligned

        if (kc == 7) {
            // epilogue for this 256-wide n pass: tanh + weighted reduce
            int slot = tg + 4 * (wid >> 1);
            int soff = ((bm + m0) / T - bA) * 512;
            #pragma unroll
            for (int mt = 0; mt < 4; mt++) {
                int row = m0 + mt * 16 + gr;
                float p0 = 0.f, p1 = 0.f;
                #pragma unroll
                for (int nt = 0; nt < 8; nt++) {
                    int n = ni * 256 + n0 + nt * 8 + tg * 2;
                    float sp0 = sm[SP_OFF + soff + n], sp1 = sm[SP_OFF + soff + n + 1];
                    float sv0 = sm[SV_OFF + soff + n], sv1 = sm[SV_OFF + soff + n + 1];
                    p0 = fmaf(tanh_fast(sp0 + acc[mt][nt][0]), sv0, p0);
                    p0 = fmaf(tanh_fast(sp1 + acc[mt][nt][1]), sv1, p0);
                    p1 = fmaf(tanh_fast(sp0 + acc[mt][nt][2]), sv0, p1);
                    p1 = fmaf(tanh_fast(sp1 + acc[mt][nt][3]), sv1, p1);
                }
                if (ni == 0) {
                    sm[RED_OFF + row * 17 + slot] = p0;
                    sm[RED_OFF + (row + 8) * 17 + slot] = p1;
                } else {
                    sm[RED_OFF + row * 17 + slot] += p0;
                    sm[RED_OFF + (row + 8) * 17 + slot] += p1;
                }
            }
        }
    }
    __syncthreads();
    if (tid < 128) {
        float s = 0.f;
        #pragma unroll
        for (int j = 0; j < 16; j++) s += sm[RED_OFF + tid * 17 + j];
        score[bm + tid] = s;
    }
}

// =====================================================================
// Generic SIMT GEMM: C[M,N] = A[M,K] @ W[N,K]^T + bias[N].
// =====================================================================
#define BM 64
#define BN 64
#define BKK 16

__global__ __launch_bounds__(256) void gemm_bias_kernel(
    const float* __restrict__ A, int lda,
    const float* __restrict__ W, int ldw,
    const float* __restrict__ bias,
    float* __restrict__ C,
    int M, int N, int K)
{
    __shared__ float As[BM][BKK];
    __shared__ float Bs[BKK][BN];

    int tid = threadIdx.x;
    int tx = tid & 15, ty = tid >> 4;
    int bm = blockIdx.y * BM;
    int bn = blockIdx.x * BN;
    int lrow = tid >> 2;
    int lcol = (tid & 3) * 4;

    float acc[4][4];
#pragma unroll
    for (int i = 0; i < 4; i++)
#pragma unroll
        for (int j = 0; j < 4; j++) acc[i][j] = 0.f;

    for (int k0 = 0; k0 < K; k0 += BKK) {
        float4 av = *(const float4*)(A + (size_t)(bm + lrow) * lda + k0 + lcol);
        *(float4*)&As[lrow][lcol] = av;
        float4 bv;
        if (bn + lrow < N)
            bv = *(const float4*)(W + (size_t)(bn + lrow) * ldw + k0 + lcol);
        else
            bv = make_float4(0.f, 0.f, 0.f, 0.f);
        Bs[lcol + 0][lrow] = bv.x;
        Bs[lcol + 1][lrow] = bv.y;
        Bs[lcol + 2][lrow] = bv.z;
        Bs[lcol + 3][lrow] = bv.w;
        __syncthreads();
#pragma unroll
        for (int k = 0; k < BKK; k++) {
            float a[4], bq[4];
#pragma unroll
            for (int i = 0; i < 4; i++) a[i] = As[ty * 4 + i][k];
#pragma unroll
            for (int j = 0; j < 4; j++) bq[j] = Bs[k][tx * 4 + j];
#pragma unroll
            for (int i = 0; i < 4; i++)
#pragma unroll
                for (int j = 0; j < 4; j++) acc[i][j] = fmaf(a[i], bq[j], acc[i][j]);
        }
        __syncthreads();
    }

#pragma unroll
    for (int i = 0; i < 4; i++) {
        int m = bm + ty * 4 + i;
#pragma unroll
        for (int j = 0; j < 4; j++) {
            int n = bn + tx * 4 + j;
            if (n < N)
                C[(size_t)m * N + n] = acc[i][j] + bias[n];
        }
    }
}

// =====================================================================
// Softmax over masked scores + context. One block per batch b.
// =====================================================================
__global__ __launch_bounds__(256) void softmax_ctx_kernel(
    const float* __restrict__ score, const int* __restrict__ ids,
    const float* __restrict__ enc, float* __restrict__ ctx, int T)
{
    int b = blockIdx.x;
    int tid = threadIdx.x;
    __shared__ float sa[256];
    __shared__ float rbuf[256];

    float v = -INFINITY;
    if (tid < T) {
        float s = score[b * T + tid];
        if (ids[b * T + tid] == 0) s = NEGV;
        sa[tid] = s;
        v = s;
    }
    rbuf[tid] = v;
    __syncthreads();
    for (int s = 128; s > 0; s >>= 1) {
        if (tid < s) rbuf[tid] = fmaxf(rbuf[tid], rbuf[tid + s]);
        __syncthreads();
    }
    float mx = rbuf[0];
    __syncthreads();

    float e = 0.f;
    if (tid < T) e = expf(sa[tid] - mx);
    rbuf[tid] = e;
    __syncthreads();
    for (int s = 128; s > 0; s >>= 1) {
        if (tid < s) rbuf[tid] += rbuf[tid + s];
        __syncthreads();
    }
    float inv = 1.0f / rbuf[0];
    __syncthreads();
    if (tid < T) sa[tid] = e * inv;
    __syncthreads();

    for (int h = tid; h < HD; h += 256) {
        float acc = 0.f;
        for (int t = 0; t < T; t++)
            acc = fmaf(sa[t], enc[((size_t)b * T + t) * HD + h], acc);
        ctx[b * HD + h] = acc;
    }
}

// =====================================================================
// Assemble GRU input x = [emb | ctx_u | ctx_b | ctx_p | db]
// =====================================================================
__global__ void assemble_x_kernel(
    const int* __restrict__ w, const float* __restrict__ emb_table,
    const float* __restrict__ db)
{
    int idx = blockIdx.x * blockDim.x + threadIdx.x;
    if (idx >= BB * XD) return;
    int b = idx / XD, c = idx % XD;
    float v;
    if (c < 512)       v = emb_table[(size_t)w[b] * 512 + c];
    else if (c < 1024) v = g_ctx_u[b * HD + c - 512];
    else if (c < 1536) v = g_ctx_b[b * HD + c - 1024];
    else if (c < 2048) v = g_ctx_p[b * HD + c - 1536];
    else               v = db[b * PTRD + (c - 2048)];
    g_x[idx] = v;
}

// =====================================================================
// GRU gate combine
// =====================================================================
__global__ void gru_gate_kernel(const float* __restrict__ h0)
{
    int idx = blockIdx.x * blockDim.x + threadIdx.x;
    if (idx >= BB * HD) return;
    int b = idx / HD, i = idx % HD;
    const float* gi = g_gi + (size_t)b * G3;
    const float* gh = g_gh + (size_t)b * G3;
    float r = 1.f / (1.f + expf(-(gi[i] + gh[i])));
    float z = 1.f / (1.f + expf(-(gi[512 + i] + gh[512 + i])));
    float n = tanhf(gi[1024 + i] + r * gh[1024 + i]);
    g_hnew[idx] = (1.f - z) * n + z * h0[idx];
}

// =====================================================================
// Final: scatter cps, log-softmax over [gen | cps], merge + OOV.
// =====================================================================
__global__ __launch_bounds__(256) void final_kernel(
    const int* __restrict__ bspn_ids, const int* __restrict__ nounk,
    float* __restrict__ out)
{
    int b = blockIdx.x;
    int tid = threadIdx.x;
    __shared__ float s_cps[VD + TB];
    __shared__ float s_cpm[TB];
    __shared__ int   s_nk[TB];
    __shared__ float rbuf[256];

    for (int i = tid; i < VD + TB; i += 256) s_cps[i] = 0.f;
    if (tid < TB) {
        float c = g_cpraw[b * TB + tid];
        if (bspn_ids[b * TB + tid] == 0) c = NEGV;
        s_cpm[tid] = c;
        s_nk[tid] = nounk[b * TB + tid];
    }
    __syncthreads();
    if (tid == 0) {
        for (int j = 0; j < TB; j++) {
            int nk = s_nk[j];
            float c = s_cpm[j];
            if (nk < VD) s_cps[nk] += c;
            else         s_cps[VD + j] = c;
        }
    }
    __syncthreads();

    const float* genb = g_gen + (size_t)b * VD;
    float mx = -INFINITY;
    for (int i = tid; i < VD; i += 256) mx = fmaxf(mx, genb[i]);
    for (int i = tid; i < VD + TB; i += 256) mx = fmaxf(mx, s_cps[i]);
    rbuf[tid] = mx;
    __syncthreads();
    for (int s = 128; s > 0; s >>= 1) {
        if (tid < s) rbuf[tid] = fmaxf(rbuf[tid], rbuf[tid + s]);
        __syncthreads();
    }
    mx = rbuf[0];
    __syncthreads();
    float sm = 0.f;
    for (int i = tid; i < VD; i += 256) sm += expf(genb[i] - mx);
    for (int i = tid; i < VD + TB; i += 256) sm += expf(s_cps[i] - mx);
    rbuf[tid] = sm;
    __syncthreads();
    for (int s = 128; s > 0; s >>= 1) {
        if (tid < s) rbuf[tid] += rbuf[tid + s];
        __syncthreads();
    }
    float lse = mx + logf(rbuf[0]);
    __syncthreads();

    float* outb = out + (size_t)b * VOOVD;
    for (int n = tid; n < VD; n += 256) {
        float a = genb[n], c = s_cps[n];
        float m2 = fmaxf(a, c);
        outb[n] = m2 + logf(expf(a - m2) + expf(c - m2)) - lse;
    }
    for (int k = tid; k < VOOVD - VD; k += 256) {
        float add = 0.f;
        int target = VD + k;
        for (int j = 0; j < TB; j++)
            if (s_nk[j] == target) add += expf(s_cpm[j] - lse);
        outb[VD + k] = (add > 0.f) ? logf(add) : NEGV;
    }
}

// =====================================================================
// Host launcher
// =====================================================================
extern "C" void kernel_launch(void* const* d_in, const int* in_sizes, int n_in,
                              void* d_out, int out_size)
{
    const int*   dec_last_w = (const int*)  d_in[0];
    const float* h0         = (const float*)d_in[1];
    const float* usdx_h     = (const float*)d_in[2];
    const float* bspn_h     = (const float*)d_in[3];
    const float* pvaspn_h   = (const float*)d_in[4];
    const float* db         = (const float*)d_in[5];
    const int*   usdx_ids   = (const int*)  d_in[6];
    const int*   bspn_ids   = (const int*)  d_in[7];
    const int*   pvaspn_ids = (const int*)  d_in[8];
    const int*   bspn_nounk = (const int*)  d_in[9];
    const float* emb_table  = (const float*)d_in[11];
    const float* attn_W     = (const float*)d_in[12];
    const float* attn_b     = (const float*)d_in[13];
    const float* v_w        = (const float*)d_in[14];
    const float* Wcopy_w    = (const float*)d_in[15];
    const float* Wcopy_b    = (const float*)d_in[16];
    const float* Wgen_w     = (const float*)d_in[17];
    const float* Wgen_b     = (const float*)d_in[18];
    const float* gru_W_ih   = (const float*)d_in[19];
    const float* gru_W_hh   = (const float*)d_in[20];
    const float* gru_b_ih   = (const float*)d_in[21];
    const float* gru_b_hh   = (const float*)d_in[22];
    float* out = (float*)d_out;

    float *p_, *su_, *sb_, *sp_, *cu_, *cb_, *cp_, *x_, *gi_, *gh_, *hn_, *gen_, *cpraw_;
    cudaGetSymbolAddress((void**)&p_,     g_p);
    cudaGetSymbolAddress((void**)&su_,    g_score_u);
    cudaGetSymbolAddress((void**)&sb_,    g_score_b);
    cudaGetSymbolAddress((void**)&sp_,    g_score_p);
    cudaGetSymbolAddress((void**)&cu_,    g_ctx_u);
    cudaGetSymbolAddress((void**)&cb_,    g_ctx_b);
    cudaGetSymbolAddress((void**)&cp_,    g_ctx_p);
    cudaGetSymbolAddress((void**)&x_,     g_x);
    cudaGetSymbolAddress((void**)&gi_,    g_gi);
    cudaGetSymbolAddress((void**)&gh_,    g_gh);
    cudaGetSymbolAddress((void**)&hn_,    g_hnew);
    cudaGetSymbolAddress((void**)&gen_,   g_gen);
    cudaGetSymbolAddress((void**)&cpraw_, g_cpraw);

    cudaFuncSetAttribute(score_tf32_kernel,
                         cudaFuncAttributeMaxDynamicSharedMemorySize, SMEM_SZ);

    // 1) p = h0 @ W1^T + attn_b   (W1 = attn_W[:, :H], ldw = 2H)
    gemm_bias_kernel<<<dim3(HD / BN, BB / BM), 256>>>(
        h0, HD, attn_W, 2 * HD, attn_b, p_, BB, HD, HD);

    // 2) attention scores on tensor cores (pipelined tf32 mma.sync)
    score_tf32_kernel<<<BB * TU / 128, 256, SMEM_SZ>>>(
        usdx_h, attn_W + HD, 2 * HD, p_, HD, v_w, 0, su_, TU);
    score_tf32_kernel<<<BB * TB / 128, 256, SMEM_SZ>>>(
        bspn_h, attn_W + HD, 2 * HD, p_, HD, v_w, 0, sb_, TB);
    score_tf32_kernel<<<BB * TP / 128, 256, SMEM_SZ>>>(
        pvaspn_h, attn_W + HD, 2 * HD, p_, HD, v_w, 0, sp_, TP);

    // 3) masked softmax + context
    softmax_ctx_kernel<<<BB, 256>>>(su_, usdx_ids,   usdx_h,   cu_, TU);
    softmax_ctx_kernel<<<BB, 256>>>(sb_, bspn_ids,   bspn_h,   cb_, TB);
    softmax_ctx_kernel<<<BB, 256>>>(sp_, pvaspn_ids, pvaspn_h, cp_, TP);

    // 4) GRU
    assemble_x_kernel<<<(BB * XD + 255) / 256, 256>>>(dec_last_w, emb_table, db);
    gemm_bias_kernel<<<dim3(G3 / BN, BB / BM), 256>>>(
        x_, XD, gru_W_ih, XD, gru_b_ih, gi_, BB, G3, XD);
    gemm_bias_kernel<<<dim3(G3 / BN, BB / BM), 256>>>(
        h0, HD, gru_W_hh, HD, gru_b_hh, gh_, BB, G3, HD);
    gru_gate_kernel<<<(BB * HD + 255) / 256, 256>>>(h0);

    // 5) gen logits
    gemm_bias_kernel<<<dim3((VD + BN - 1) / BN, BB / BM), 256>>>(
        hn_, HD, Wgen_w, HD, Wgen_b, gen_, BB, VD, HD);

    // 6) cp_raw[b,t] = hnew[b] . tanh(Wcopy_b + Wcopy_w @ bspn_h[b,t])
    score_tf32_kernel<<<BB * TB / 128, 256, SMEM_SZ>>>(
        bspn_h, Wcopy_w, HD, Wcopy_b, 0, hn_, HD, cpraw_, TB);

    // 7) final scatter + log-softmax + merge
    final_kernel<<<BB, 256>>>(bspn_ids, bspn_nounk, out);
}

// round 6
// speedup vs baseline: 3.4731x; 1.3192x over previous
#include <cuda_runtime.h>
#include <cuda_bf16.h>
#include <math.h>
#include <stdint.h>

// ---- problem constants ----
#define BB    128
#define TU    256
#define TB    128
#define TP    64
#define HD    512
#define VD    3000
#define VOOVD 3400
#define PTRD  32
#define XD    2080   // E + 3H + PTR
#define G3    1536   // 3H
#define NEGV  (-1e20f)

// ---- scratch (device globals; no allocation allowed) ----
__device__ float g_p[BB * HD];
__device__ float g_score_u[BB * TU];
__device__ float g_score_b[BB * TB];
__device__ float g_score_p[BB * TP];
__device__ float g_ctx_u[BB * HD];
__device__ float g_ctx_b[BB * HD];
__device__ float g_ctx_p[BB * HD];
__device__ float g_x[BB * XD];
__device__ float g_gi[BB * G3];
__device__ float g_gh[BB * G3];
__device__ float g_hnew[BB * HD];
__device__ float g_gen[BB * VD];
__device__ float g_cpraw[BB * TB];
// staged bf16 weights: [0]=attn_W2 (512x512), [1]=Wcopy (512x512), row-major n,k
__device__ __nv_bfloat16 g_wsc[2][512 * 512];

// =====================================================================
// helpers (sm_80+ PTX; compiles at plain compute_103)
// =====================================================================
__device__ __forceinline__ void mma_bf16(float* d,
    uint32_t a0, uint32_t a1, uint32_t a2, uint32_t a3,
    uint32_t b0, uint32_t b1)
{
    asm volatile(
        "mma.sync.aligned.m16n8k16.row.col.f32.bf16.bf16.f32 "
        "{%0,%1,%2,%3}, {%4,%5,%6,%7}, {%8,%9}, {%0,%1,%2,%3};"
        : "+f"(d[0]), "+f"(d[1]), "+f"(d[2]), "+f"(d[3])
        : "r"(a0), "r"(a1), "r"(a2), "r"(a3), "r"(b0), "r"(b1));
}
__device__ __forceinline__ void cpa16(uint32_t s, const void* g) {
    asm volatile("cp.async.cg.shared.global [%0], [%1], 16;" :: "r"(s), "l"(g));
}
__device__ __forceinline__ void cpa_commit() {
    asm volatile("cp.async.commit_group;");
}
__device__ __forceinline__ void cpa_wait1() {
    asm volatile("cp.async.wait_group 1;");
}
__device__ __forceinline__ float tanh_fast(float x) {
    float y; asm("tanh.approx.f32 %0, %1;" : "=f"(y) : "f"(x)); return y;
}
__device__ __forceinline__ uint32_t pack_bf16(float a, float b) {
    __nv_bfloat162 t = __floats2bfloat162_rn(a, b);
    return *(uint32_t*)&t;
}

// =====================================================================
// bf16 tensor-core score body:
//   score[bm+m] = sum_n vvec[b,n] * tanh(addv[b,n] + sum_k Enc[m,k]*W[n,k])
// Block = 128 M-rows x full N=512 (two 256-wide passes).
// A (128x512) resident in smem bf16, converted once from f32.
// B streamed as 64-k bf16 chunks via cp.async double buffer from staged W.
// A row stride 520 halves, B row stride 72 halves: word pattern 4r+t,
// conflict-free for all fragment loads.
// =====================================================================
#define A_OFF   0                          // 128 * 1040 B = 133120
#define B_OFF   133120
#define B_BUF_B 36864                      // 256 * 144 B
#define SP_OFF  (B_OFF + 2 * B_BUF_B)      // 206848
#define SV_OFF  (SP_OFF + 4096)            // 210944
#define RED_OFF (SV_OFF + 4096)            // 215040 (128*17*4 = 8704)
#define SMEM_SZ 223744

__device__ __forceinline__ void b_prefetch(
    const __nv_bfloat16* __restrict__ Wb, int ni, int kc, int bb,
    uint32_t smb, int tid)
{
    const __nv_bfloat16* src = Wb + (size_t)(ni * 256) * 512 + kc * 64;
    uint32_t dst = smb + B_OFF + bb * B_BUF_B;
    #pragma unroll
    for (int it = 0; it < 8; it++) {
        int idx = tid + it * 256;
        int row = idx >> 3, ch = idx & 7;
        cpa16(dst + row * 144 + ch * 16, src + (size_t)row * 512 + ch * 8);
    }
    cpa_commit();
}

__device__ __forceinline__ void score_body(
    const float* __restrict__ Enc,
    const __nv_bfloat16* __restrict__ Wb,
    const float* __restrict__ addv, int a_stride,
    const float* __restrict__ vvec, int v_stride,
    float* __restrict__ score, int T, int bm)
{
    extern __shared__ char smc[];
    uint32_t smb = (uint32_t)__cvta_generic_to_shared(smc);
    float* smf = (float*)smc;
    int tid = threadIdx.x;
    int wid = tid >> 5, lane = tid & 31;
    int gr = lane >> 2, tg = lane & 3;
    int bA = bm / T;

    int m0 = (wid & 1) * 64;       // warp m offset (2 m-warps)
    int n0 = (wid >> 1) * 64;      // warp n offset within 256 (4 n-warps)

    // kick off first two B chunks
    b_prefetch(Wb, 0, 0, 0, smb, tid);
    b_prefetch(Wb, 0, 1, 1, smb, tid);

    // preload addv/vvec for the (up to 2) batch rows this block spans
    for (int i = tid; i < 1024; i += 256) {
        int sl = i >> 9, n = i & 511;
        int bs = (bm + sl * 64) / T;
        smf[(SP_OFF >> 2) + i] = addv[(size_t)bs * a_stride + n];
        smf[(SV_OFF >> 2) + i] = vvec[(size_t)bs * v_stride + n];
    }

    // A fill: 128 rows x 512 f32 -> bf16, once (row stride 1040 B)
    for (int it = 0; it < 64; it++) {
        int idx = tid + it * 256;               // 0..16383 float4s
        int row = idx >> 7, k = (idx & 127) << 2;
        float4 v = *(const float4*)(Enc + (size_t)(bm + row) * 512 + k);
        uint2 pk = make_uint2(pack_bf16(v.x, v.y), pack_bf16(v.z, v.w));
        *(uint2*)(smc + A_OFF + row * 1040 + k * 2) = pk;
    }
    __syncthreads();

    const uint32_t* Au = (const uint32_t*)(smc + A_OFF);
    float acc[4][8][4];

    for (int ph = 0; ph < 16; ph++) {
        int ni = ph >> 3, kc = ph & 7, bb = ph & 1;
        if (kc == 0) {
            #pragma unroll
            for (int mt = 0; mt < 4; mt++)
                #pragma unroll
                for (int nt = 0; nt < 8; nt++)
                    #pragma unroll
                    for (int q = 0; q < 4; q++) acc[mt][nt][q] = 0.f;
        }
        cpa_wait1();
        __syncthreads();

        const uint32_t* Bu = (const uint32_t*)(smc + B_OFF + bb * B_BUF_B);
        #pragma unroll
        for (int kk = 0; kk < 4; kk++) {
            int kw = kk * 8 + tg;               // word within 64-k chunk
            uint32_t bf[8][2];
            #pragma unroll
            for (int nt = 0; nt < 8; nt++) {
                int bn = n0 + nt * 8 + gr;
                bf[nt][0] = Bu[bn * 36 + kw];
                bf[nt][1] = Bu[bn * 36 + kw + 4];
            }
            int aw = kc * 32 + kw;              // word within full K=512
            #pragma unroll
            for (int mt = 0; mt < 4; mt++) {
                int ar = m0 + mt * 16 + gr;
                uint32_t a0 = Au[ar * 260 + aw];
                uint32_t a1 = Au[(ar + 8) * 260 + aw];
                uint32_t a2 = Au[ar * 260 + aw + 4];
                uint32_t a3 = Au[(ar + 8) * 260 + aw + 4];
                #pragma unroll
                for (int nt = 0; nt < 8; nt++)
                    mma_bf16(acc[mt][nt], a0, a1, a2, a3, bf[nt][0], bf[nt][1]);
            }
        }
        __syncthreads();

        int ph2 = ph + 2;
        if (ph2 < 16)
            b_prefetch(Wb, ph2 >> 3, ph2 & 7, bb, smb, tid);
        else
            cpa_commit();   // empty group keeps wait accounting aligned

        if (kc == 7) {
            // epilogue for this 256-wide n pass: tanh + weighted reduce
            int slot = tg + 4 * (wid >> 1);
            int soff = ((bm + m0) / T - bA) * 512;
            const float* sp = smf + (SP_OFF >> 2) + soff;
            const float* sv = smf + (SV_OFF >> 2) + soff;
            float* red = smf + (RED_OFF >> 2);
            #pragma unroll
            for (int mt = 0; mt < 4; mt++) {
                int row = m0 + mt * 16 + gr;
                float p0 = 0.f, p1 = 0.f;
                #pragma unroll
                for (int nt = 0; nt < 8; nt++) {
                    int n = ni * 256 + n0 + nt * 8 + tg * 2;
                    float sp0 = sp[n], sp1 = sp[n + 1];
                    float sv0 = sv[n], sv1 = sv[n + 1];
                    p0 = fmaf(tanh_fast(sp0 + acc[mt][nt][0]), sv0, p0);
                    p0 = fmaf(tanh_fast(sp1 + acc[mt][nt][1]), sv1, p0);
                    p1 = fmaf(tanh_fast(sp0 + acc[mt][nt][2]), sv0, p1);
                    p1 = fmaf(tanh_fast(sp1 + acc[mt][nt][3]), sv1, p1);
                }
                if (ni == 0) {
                    red[row * 17 + slot] = p0;
                    red[(row + 8) * 17 + slot] = p1;
                } else {
                    red[row * 17 + slot] += p0;
                    red[(row + 8) * 17 + slot] += p1;
                }
            }
        }
    }
    __syncthreads();
    if (tid < 128) {
        float* red = smf + (RED_OFF >> 2);
        float s = 0.f;
        #pragma unroll
        for (int j = 0; j < 16; j++) s += red[tid * 17 + j];
        score[bm + tid] = s;
    }
}

// combined attention-score launch: segments [0,256)=usdx, [256,384)=bspn,
// [384,448)=pvaspn
__global__ __launch_bounds__(256, 1) void score_attn_kernel(
    const float* __restrict__ usdx, const float* __restrict__ bspn,
    const float* __restrict__ pv,
    const float* __restrict__ p, const float* __restrict__ vw,
    float* __restrict__ su, float* __restrict__ sb2, float* __restrict__ sp2)
{
    int bx = blockIdx.x;
    const float* enc; float* out; int T, bm;
    if (bx < 256)      { enc = usdx; out = su;  T = TU; bm = bx * 128; }
    else if (bx < 384) { enc = bspn; out = sb2; T = TB; bm = (bx - 256) * 128; }
    else               { enc = pv;   out = sp2; T = TP; bm = (bx - 384) * 128; }
    score_body(enc, g_wsc[0], p, 512, vw, 0, out, T, bm);
}

__global__ __launch_bounds__(256, 1) void score_cp_kernel(
    const float* __restrict__ bspn, const float* __restrict__ wcb,
    const float* __restrict__ hnew, float* __restrict__ out)
{
    score_body(bspn, g_wsc[1], wcb, 0, hnew, 512, out, TB, blockIdx.x * 128);
}

// =====================================================================
// Stage weights to bf16: [0]=attn_W[:,512:1024], [1]=Wcopy_w
// =====================================================================
__global__ void stage_w_kernel(const float* __restrict__ attn_W,
                               const float* __restrict__ Wcopy_w)
{
    int idx = blockIdx.x * blockDim.x + threadIdx.x;
    if (idx >= 2 * 262144) return;
    int m = idx >> 18, r = idx & 262143;
    int n = r >> 9, k = r & 511;
    float v = m ? Wcopy_w[n * 512 + k] : attn_W[n * 1024 + 512 + k];
    g_wsc[m][r] = __float2bfloat16(v);
}

// =====================================================================
// Generic SIMT GEMM: C[M,N] = A[M,K] @ W[N,K]^T + bias[N].
// =====================================================================
#define BM 64
#define BN 64
#define BKK 16

__global__ __launch_bounds__(256) void gemm_bias_kernel(
    const float* __restrict__ A, int lda,
    const float* __restrict__ W, int ldw,
    const float* __restrict__ bias,
    float* __restrict__ C,
    int M, int N, int K)
{
    __shared__ float As[BM][BKK];
    __shared__ float Bs[BKK][BN];

    int tid = threadIdx.x;
    int tx = tid & 15, ty = tid >> 4;
    int bm = blockIdx.y * BM;
    int bn = blockIdx.x * BN;
    int lrow = tid >> 2;
    int lcol = (tid & 3) * 4;

    float acc[4][4];
#pragma unroll
    for (int i = 0; i < 4; i++)
#pragma unroll
        for (int j = 0; j < 4; j++) acc[i][j] = 0.f;

    for (int k0 = 0; k0 < K; k0 += BKK) {
        float4 av = *(const float4*)(A + (size_t)(bm + lrow) * lda + k0 + lcol);
        *(float4*)&As[lrow][lcol] = av;
        float4 bv;
        if (bn + lrow < N)
            bv = *(const float4*)(W + (size_t)(bn + lrow) * ldw + k0 + lcol);
        else
            bv = make_float4(0.f, 0.f, 0.f, 0.f);
        Bs[lcol + 0][lrow] = bv.x;
        Bs[lcol + 1][lrow] = bv.y;
        Bs[lcol + 2][lrow] = bv.z;
        Bs[lcol + 3][lrow] = bv.w;
        __syncthreads();
#pragma unroll
        for (int k = 0; k < BKK; k++) {
            float a[4], bq[4];
#pragma unroll
            for (int i = 0; i < 4; i++) a[i] = As[ty * 4 + i][k];
#pragma unroll
            for (int j = 0; j < 4; j++) bq[j] = Bs[k][tx * 4 + j];
#pragma unroll
            for (int i = 0; i < 4; i++)
#pragma unroll
                for (int j = 0; j < 4; j++) acc[i][j] = fmaf(a[i], bq[j], acc[i][j]);
        }
        __syncthreads();
    }

#pragma unroll
    for (int i = 0; i < 4; i++) {
        int m = bm + ty * 4 + i;
#pragma unroll
        for (int j = 0; j < 4; j++) {
            int n = bn + tx * 4 + j;
            if (n < N)
                C[(size_t)m * N + n] = acc[i][j] + bias[n];
        }
    }
}

// =====================================================================
// Softmax over masked scores + context. One block per batch b.
// =====================================================================
__global__ __launch_bounds__(256) void softmax_ctx_kernel(
    const float* __restrict__ score, const int* __restrict__ ids,
    const float* __restrict__ enc, float* __restrict__ ctx, int T)
{
    int b = blockIdx.x;
    int tid = threadIdx.x;
    __shared__ float sa[256];
    __shared__ float rbuf[256];

    float v = -INFINITY;
    if (tid < T) {
        float s = score[b * T + tid];
        if (ids[b * T + tid] == 0) s = NEGV;
        sa[tid] = s;
        v = s;
    }
    rbuf[tid] = v;
    __syncthreads();
    for (int s = 128; s > 0; s >>= 1) {
        if (tid < s) rbuf[tid] = fmaxf(rbuf[tid], rbuf[tid + s]);
        __syncthreads();
    }
    float mx = rbuf[0];
    __syncthreads();

    float e = 0.f;
    if (tid < T) e = expf(sa[tid] - mx);
    rbuf[tid] = e;
    __syncthreads();
    for (int s = 128; s > 0; s >>= 1) {
        if (tid < s) rbuf[tid] += rbuf[tid + s];
        __syncthreads();
    }
    float inv = 1.0f / rbuf[0];
    __syncthreads();
    if (tid < T) sa[tid] = e * inv;
    __syncthreads();

    for (int h = tid; h < HD; h += 256) {
        float acc = 0.f;
        for (int t = 0; t < T; t++)
            acc = fmaf(sa[t], enc[((size_t)b * T + t) * HD + h], acc);
        ctx[b * HD + h] = acc;
    }
}

// =====================================================================
// Assemble GRU input x = [emb | ctx_u | ctx_b | ctx_p | db]
// =====================================================================
__global__ void assemble_x_kernel(
    const int* __restrict__ w, const float* __restrict__ emb_table,
    const float* __restrict__ db)
{
    int idx = blockIdx.x * blockDim.x + threadIdx.x;
    if (idx >= BB * XD) return;
    int b = idx / XD, c = idx % XD;
    float v;
    if (c < 512)       v = emb_table[(size_t)w[b] * 512 + c];
    else if (c < 1024) v = g_ctx_u[b * HD + c - 512];
    else if (c < 1536) v = g_ctx_b[b * HD + c - 1024];
    else if (c < 2048) v = g_ctx_p[b * HD + c - 1536];
    else               v = db[b * PTRD + (c - 2048)];
    g_x[idx] = v;
}

// =====================================================================
// GRU gate combine
// =====================================================================
__global__ void gru_gate_kernel(const float* __restrict__ h0)
{
    int idx = blockIdx.x * blockDim.x + threadIdx.x;
    if (idx >= BB * HD) return;
    int b = idx / HD, i = idx % HD;
    const float* gi = g_gi + (size_t)b * G3;
    const float* gh = g_gh + (size_t)b * G3;
    float r = 1.f / (1.f + expf(-(gi[i] + gh[i])));
    float z = 1.f / (1.f + expf(-(gi[512 + i] + gh[512 + i])));
    float n = tanhf(gi[1024 + i] + r * gh[1024 + i]);
    g_hnew[idx] = (1.f - z) * n + z * h0[idx];
}

// =====================================================================
// Final: scatter cps, log-softmax over [gen | cps], merge + OOV.
// =====================================================================
__global__ __launch_bounds__(256) void final_kernel(
    const int* __restrict__ bspn_ids, const int* __restrict__ nounk,
    float* __restrict__ out)
{
    int b = blockIdx.x;
    int tid = threadIdx.x;
    __shared__ float s_cps[VD + TB];
    __shared__ float s_cpm[TB];
    __shared__ int   s_nk[TB];
    __shared__ float rbuf[256];

    for (int i = tid; i < VD + TB; i += 256) s_cps[i] = 0.f;
    if (tid < TB) {
        float c = g_cpraw[b * TB + tid];
        if (bspn_ids[b * TB + tid] == 0) c = NEGV;
        s_cpm[tid] = c;
        s_nk[tid] = nounk[b * TB + tid];
    }
    __syncthreads();
    if (tid == 0) {
        for (int j = 0; j < TB; j++) {
            int nk = s_nk[j];
            float c = s_cpm[j];
            if (nk < VD) s_cps[nk] += c;
            else         s_cps[VD + j] = c;
        }
    }
    __syncthreads();

    const float* genb = g_gen + (size_t)b * VD;
    float mx = -INFINITY;
    for (int i = tid; i < VD; i += 256) mx = fmaxf(mx, genb[i]);
    for (int i = tid; i < VD + TB; i += 256) mx = fmaxf(mx, s_cps[i]);
    rbuf[tid] = mx;
    __syncthreads();
    for (int s = 128; s > 0; s >>= 1) {
        if (tid < s) rbuf[tid] = fmaxf(rbuf[tid], rbuf[tid + s]);
        __syncthreads();
    }
    mx = rbuf[0];
    __syncthreads();
    float sm = 0.f;
    for (int i = tid; i < VD; i += 256) sm += expf(genb[i] - mx);
    for (int i = tid; i < VD + TB; i += 256) sm += expf(s_cps[i] - mx);
    rbuf[tid] = sm;
    __syncthreads();
    for (int s = 128; s > 0; s >>= 1) {
        if (tid < s) rbuf[tid] += rbuf[tid + s];
        __syncthreads();
    }
    float lse = mx + logf(rbuf[0]);
    __syncthreads();

    float* outb = out + (size_t)b * VOOVD;
    for (int n = tid; n < VD; n += 256) {
        float a = genb[n], c = s_cps[n];
        float m2 = fmaxf(a, c);
        outb[n] = m2 + logf(expf(a - m2) + expf(c - m2)) - lse;
    }
    for (int k = tid; k < VOOVD - VD; k += 256) {
        float add = 0.f;
        int target = VD + k;
        for (int j = 0; j < TB; j++)
            if (s_nk[j] == target) add += expf(s_cpm[j] - lse);
        outb[VD + k] = (add > 0.f) ? logf(add) : NEGV;
    }
}

// =====================================================================
// Host launcher
// =====================================================================
extern "C" void kernel_launch(void* const* d_in, const int* in_sizes, int n_in,
                              void* d_out, int out_size)
{
    const int*   dec_last_w = (const int*)  d_in[0];
    const float* h0         = (const float*)d_in[1];
    const float* usdx_h     = (const float*)d_in[2];
    const float* bspn_h     = (const float*)d_in[3];
    const float* pvaspn_h   = (const float*)d_in[4];
    const float* db         = (const float*)d_in[5];
    const int*   usdx_ids   = (const int*)  d_in[6];
    const int*   bspn_ids   = (const int*)  d_in[7];
    const int*   pvaspn_ids = (const int*)  d_in[8];
    const int*   bspn_nounk = (const int*)  d_in[9];
    const float* emb_table  = (const float*)d_in[11];
    const float* attn_W     = (const float*)d_in[12];
    const float* attn_b     = (const float*)d_in[13];
    const float* v_w        = (const float*)d_in[14];
    const float* Wcopy_w    = (const float*)d_in[15];
    const float* Wcopy_b    = (const float*)d_in[16];
    const float* Wgen_w     = (const float*)d_in[17];
    const float* Wgen_b     = (const float*)d_in[18];
    const float* gru_W_ih   = (const float*)d_in[19];
    const float* gru_W_hh   = (const float*)d_in[20];
    const float* gru_b_ih   = (const float*)d_in[21];
    const float* gru_b_hh   = (const float*)d_in[22];
    float* out = (float*)d_out;

    float *p_, *su_, *sb_, *sp_, *cu_, *cb_, *cp_, *x_, *gi_, *gh_, *hn_, *gen_, *cpraw_;
    cudaGetSymbolAddress((void**)&p_,     g_p);
    cudaGetSymbolAddress((void**)&su_,    g_score_u);
    cudaGetSymbolAddress((void**)&sb_,    g_score_b);
    cudaGetSymbolAddress((void**)&sp_,    g_score_p);
    cudaGetSymbolAddress((void**)&cu_,    g_ctx_u);
    cudaGetSymbolAddress((void**)&cb_,    g_ctx_b);
    cudaGetSymbolAddress((void**)&cp_,    g_ctx_p);
    cudaGetSymbolAddress((void**)&x_,     g_x);
    cudaGetSymbolAddress((void**)&gi_,    g_gi);
    cudaGetSymbolAddress((void**)&gh_,    g_gh);
    cudaGetSymbolAddress((void**)&hn_,    g_hnew);
    cudaGetSymbolAddress((void**)&gen_,   g_gen);
    cudaGetSymbolAddress((void**)&cpraw_, g_cpraw);

    cudaFuncSetAttribute(score_attn_kernel,
                         cudaFuncAttributeMaxDynamicSharedMemorySize, SMEM_SZ);
    cudaFuncSetAttribute(score_cp_kernel,
                         cudaFuncAttributeMaxDynamicSharedMemorySize, SMEM_SZ);

    // 0) stage score weights to bf16
    stage_w_kernel<<<(2 * 262144 + 255) / 256, 256>>>(attn_W, Wcopy_w);

    // 1) p = h0 @ W1^T + attn_b   (W1 = attn_W[:, :H], ldw = 2H)
    gemm_bias_kernel<<<dim3(HD / BN, BB / BM), 256>>>(
        h0, HD, attn_W, 2 * HD, attn_b, p_, BB, HD, HD);

    // 2) all three attention scores in one bf16 tensor-core launch
    score_attn_kernel<<<448, 256, SMEM_SZ>>>(
        usdx_h, bspn_h, pvaspn_h, p_, v_w, su_, sb_, sp_);

    // 3) masked softmax + context
    softmax_ctx_kernel<<<BB, 256>>>(su_, usdx_ids,   usdx_h,   cu_, TU);
    softmax_ctx_kernel<<<BB, 256>>>(sb_, bspn_ids,   bspn_h,   cb_, TB);
    softmax_ctx_kernel<<<BB, 256>>>(sp_, pvaspn_ids, pvaspn_h, cp_, TP);

    // 4) GRU
    assemble_x_kernel<<<(BB * XD + 255) / 256, 256>>>(dec_last_w, emb_table, db);
    gemm_bias_kernel<<<dim3(G3 / BN, BB / BM), 256>>>(
        x_, XD, gru_W_ih, XD, gru_b_ih, gi_, BB, G3, XD);
    gemm_bias_kernel<<<dim3(G3 / BN, BB / BM), 256>>>(
        h0, HD, gru_W_hh, HD, gru_b_hh, gh_, BB, G3, HD);
    gru_gate_kernel<<<(BB * HD + 255) / 256, 256>>>(h0);

    // 5) gen logits
    gemm_bias_kernel<<<dim3((VD + BN - 1) / BN, BB / BM), 256>>>(
        hn_, HD, Wgen_w, HD, Wgen_b, gen_, BB, VD, HD);

    // 6) cp_raw[b,t] = hnew[b] . tanh(Wcopy_b + Wcopy_w @ bspn_h[b,t])
    score_cp_kernel<<<BB * TB / 128, 256, SMEM_SZ>>>(
        bspn_h, Wcopy_b, hn_, cpraw_);

    // 7) final scatter + log-softmax + merge
    final_kernel<<<BB, 256>>>(bspn_ids, bspn_nounk, out);
}

// round 8
// speedup vs baseline: 6.5431x; 1.8840x over previous
#include <cuda_runtime.h>
#include <cuda_bf16.h>
#include <math.h>
#include <stdint.h>

// ---- problem constants ----
#define BB    128
#define TU    256
#define TB    128
#define TP    64
#define HD    512
#define VD    3000
#define VOOVD 3400
#define PTRD  32
#define XDP   2112   // padded GRU input width (2080 -> 2112)
#define G3    1536
#define NEGV  (-1e20f)

// ---- scratch (device globals; no allocation allowed) ----
__device__ float g_p[BB * HD];
__device__ float g_score_u[BB * TU];   // scores, then softmax weights in place
__device__ float g_score_b[BB * TB];
__device__ float g_score_p[BB * TP];
__device__ float g_ctx_u[BB * HD];
__device__ float g_ctx_b[BB * HD];
__device__ float g_ctx_p[BB * HD];
__device__ float g_gi[BB * G3];
__device__ float g_gh[BB * G3];
__device__ float g_hnew[BB * HD];
__device__ float g_gen[BB * VD];
__device__ float g_cpraw[BB * TB];

// bf16 staged operands
__device__ __nv_bfloat16 g_wsc[2][512 * 512];     // [0]=attn_W2, [1]=Wcopy (score path)
__device__ __nv_bfloat16 g_w1b[512 * 512];        // attn_W1
__device__ __nv_bfloat16 g_wihb[G3 * XDP];        // gru_W_ih padded K
__device__ __nv_bfloat16 g_whhb[G3 * 512];
__device__ __nv_bfloat16 g_wgenb[3008 * 512];     // padded N rows (zeros >= 3000)
__device__ __nv_bfloat16 g_h0b[BB * 512];
__device__ __nv_bfloat16 g_xb[BB * XDP];
__device__ __nv_bfloat16 g_hnb[BB * 512];

// =====================================================================
// helpers (sm_80+ PTX; compiles at plain compute_103)
// =====================================================================
__device__ __forceinline__ void mma_bf16(float* d,
    uint32_t a0, uint32_t a1, uint32_t a2, uint32_t a3,
    uint32_t b0, uint32_t b1)
{
    asm volatile(
        "mma.sync.aligned.m16n8k16.row.col.f32.bf16.bf16.f32 "
        "{%0,%1,%2,%3}, {%4,%5,%6,%7}, {%8,%9}, {%0,%1,%2,%3};"
        : "+f"(d[0]), "+f"(d[1]), "+f"(d[2]), "+f"(d[3])
        : "r"(a0), "r"(a1), "r"(a2), "r"(a3), "r"(b0), "r"(b1));
}
__device__ __forceinline__ void cpa16(uint32_t s, const void* g) {
    asm volatile("cp.async.cg.shared.global [%0], [%1], 16;" :: "r"(s), "l"(g));
}
__device__ __forceinline__ void cpa_commit() {
    asm volatile("cp.async.commit_group;");
}
__device__ __forceinline__ void cpa_wait1() {
    asm volatile("cp.async.wait_group 1;");
}
__device__ __forceinline__ float tanh_fast(float x) {
    float y; asm("tanh.approx.f32 %0, %1;" : "=f"(y) : "f"(x)); return y;
}
__device__ __forceinline__ uint32_t pack_bf16(float a, float b) {
    __nv_bfloat162 t = __floats2bfloat162_rn(a, b);
    return *(uint32_t*)&t;
}

// =====================================================================
// Stage everything to bf16 once.
// =====================================================================
#define SO1 262144
#define SO2 524288
#define SO3 786432
#define SO4 4030464   // +1536*2112
#define SO5 4816896   // +1536*512
#define SO6 6356992   // +3008*512
#define SO7 6422528   // +128*512
__global__ void stage_all_kernel(
    const float* __restrict__ attn_W, const float* __restrict__ Wcopy_w,
    const float* __restrict__ W_ih, const float* __restrict__ W_hh,
    const float* __restrict__ Wgen_w, const float* __restrict__ h0)
{
    int idx = blockIdx.x * blockDim.x + threadIdx.x;
    if (idx >= SO7) return;
    if (idx < SO1) {
        int n = idx >> 9, k = idx & 511;
        g_w1b[idx] = __float2bfloat16(attn_W[n * 1024 + k]);
    } else if (idx < SO2) {
        int r = idx - SO1; int n = r >> 9, k = r & 511;
        g_wsc[0][r] = __float2bfloat16(attn_W[n * 1024 + 512 + k]);
    } else if (idx < SO3) {
        int r = idx - SO2;
        g_wsc[1][r] = __float2bfloat16(Wcopy_w[r]);
    } else if (idx < SO4) {
        int r = idx - SO3; int n = r / XDP, k = r % XDP;
        g_wihb[r] = (k < 2080) ? __float2bfloat16(W_ih[(size_t)n * 2080 + k])
                               : __float2bfloat16(0.f);
    } else if (idx < SO5) {
        int r = idx - SO4;
        g_whhb[r] = __float2bfloat16(W_hh[r]);
    } else if (idx < SO6) {
        int r = idx - SO5; int n = r >> 9;
        g_wgenb[r] = (n < VD) ? __float2bfloat16(Wgen_w[r]) : __float2bfloat16(0.f);
    } else {
        int r = idx - SO6;
        g_h0b[r] = __float2bfloat16(h0[r]);
    }
}

// =====================================================================
// Generic bf16 MMA GEMM body: C[0:128, nbase:nbase+128] =
//   A[128,K] @ W[N,K]^T + bias.  K % 64 == 0.  Double-buffered cp.async.
// smem: 2 A-buffers + 2 B-buffers, each 128 rows x 144 B (stride 36 words).
// =====================================================================
#define GM_STR 36
#define GM_BUF 18432
#define GM_SMEM (4 * GM_BUF)   // 73728

__device__ __forceinline__ void gm_prefetch(
    const __nv_bfloat16* __restrict__ A, const __nv_bfloat16* __restrict__ W,
    int nbase, int kc, int K, int bb, uint32_t smb, int tid)
{
    const __nv_bfloat16* asrc = A + kc * 64;
    uint32_t ad = smb + bb * GM_BUF;
    #pragma unroll
    for (int it = 0; it < 4; it++) {
        int idx = tid + it * 256;
        int row = idx >> 3, ch = idx & 7;
        cpa16(ad + row * 144 + ch * 16, asrc + (size_t)row * K + ch * 8);
    }
    const __nv_bfloat16* bsrc = W + (size_t)nbase * K + kc * 64;
    uint32_t bd = smb + 2 * GM_BUF + bb * GM_BUF;
    #pragma unroll
    for (int it = 0; it < 4; it++) {
        int idx = tid + it * 256;
        int row = idx >> 3, ch = idx & 7;
        cpa16(bd + row * 144 + ch * 16, bsrc + (size_t)row * K + ch * 8);
    }
    cpa_commit();
}

__device__ __forceinline__ void gemm_mma_body(
    const __nv_bfloat16* __restrict__ A, const __nv_bfloat16* __restrict__ W,
    const float* __restrict__ bias, float* __restrict__ C,
    int ldc, int nbase, int K, int Nlim)
{
    extern __shared__ char smc[];
    uint32_t smb = (uint32_t)__cvta_generic_to_shared(smc);
    int tid = threadIdx.x;
    int wid = tid >> 5, lane = tid & 31;
    int gr = lane >> 2, tg = lane & 3;
    int m0 = (wid & 1) * 64;
    int n0 = (wid >> 1) * 32;
    int nk = K >> 6;

    gm_prefetch(A, W, nbase, 0, K, 0, smb, tid);
    gm_prefetch(A, W, nbase, 1, K, 1, smb, tid);

    float acc[4][4][4];
    #pragma unroll
    for (int mt = 0; mt < 4; mt++)
        #pragma unroll
        for (int nt = 0; nt < 4; nt++)
            #pragma unroll
            for (int q = 0; q < 4; q++) acc[mt][nt][q] = 0.f;

    for (int kc = 0; kc < nk; kc++) {
        int bb = kc & 1;
        cpa_wait1();
        __syncthreads();
        const uint32_t* Au = (const uint32_t*)(smc + bb * GM_BUF);
        const uint32_t* Bu = (const uint32_t*)(smc + 2 * GM_BUF + bb * GM_BUF);
        #pragma unroll
        for (int kk = 0; kk < 4; kk++) {
            int kw = kk * 8 + tg;
            uint32_t bf[4][2];
            #pragma unroll
            for (int nt = 0; nt < 4; nt++) {
                int bn = n0 + nt * 8 + gr;
                bf[nt][0] = Bu[bn * GM_STR + kw];
                bf[nt][1] = Bu[bn * GM_STR + kw + 4];
            }
            #pragma unroll
            for (int mt = 0; mt < 4; mt++) {
                int ar = m0 + mt * 16 + gr;
                uint32_t a0 = Au[ar * GM_STR + kw];
                uint32_t a1 = Au[(ar + 8) * GM_STR + kw];
                uint32_t a2 = Au[ar * GM_STR + kw + 4];
                uint32_t a3 = Au[(ar + 8) * GM_STR + kw + 4];
                #pragma unroll
                for (int nt = 0; nt < 4; nt++)
                    mma_bf16(acc[mt][nt], a0, a1, a2, a3, bf[nt][0], bf[nt][1]);
            }
        }
        __syncthreads();
        if (kc + 2 < nk)
            gm_prefetch(A, W, nbase, kc + 2, K, bb, smb, tid);
        else
            cpa_commit();
    }

    #pragma unroll
    for (int mt = 0; mt < 4; mt++) {
        int m = m0 + mt * 16 + gr;
        #pragma unroll
        for (int nt = 0; nt < 4; nt++) {
            int n = nbase + n0 + nt * 8 + tg * 2;
            if (n < Nlim) {
                float b0 = bias[n], b1 = bias[n + 1];
                *(float2*)(C + (size_t)m * ldc + n) =
                    make_float2(acc[mt][nt][0] + b0, acc[mt][nt][1] + b1);
                *(float2*)(C + (size_t)(m + 8) * ldc + n) =
                    make_float2(acc[mt][nt][2] + b0, acc[mt][nt][3] + b1);
            }
        }
    }
}

__global__ __launch_bounds__(256, 1) void mma_p_kernel(const float* __restrict__ attn_b)
{
    gemm_mma_body(g_h0b, g_w1b, attn_b, g_p, 512, blockIdx.x * 128, 512, 512);
}
__global__ __launch_bounds__(256, 1) void mma_gru_kernel(
    const float* __restrict__ b_ih, const float* __restrict__ b_hh)
{
    int bx = blockIdx.x;
    if (bx < 12)
        gemm_mma_body(g_xb, g_wihb, b_ih, g_gi, G3, bx * 128, XDP, G3);
    else
        gemm_mma_body(g_h0b, g_whhb, b_hh, g_gh, G3, (bx - 12) * 128, 512, G3);
}
__global__ __launch_bounds__(256, 1) void mma_gen_kernel(const float* __restrict__ Wgen_b)
{
    gemm_mma_body(g_hnb, g_wgenb, Wgen_b, g_gen, VD, blockIdx.x * 128, 512, VD);
}

// =====================================================================
// bf16 tensor-core score body (unchanged from R6, proven).
// =====================================================================
#define A_OFF   0
#define B_OFF   133120
#define B_BUF_B 36864
#define SP_OFF  (B_OFF + 2 * B_BUF_B)
#define SV_OFF  (SP_OFF + 4096)
#define RED_OFF (SV_OFF + 4096)
#define SMEM_SZ 223744

__device__ __forceinline__ void b_prefetch(
    const __nv_bfloat16* __restrict__ Wb, int ni, int kc, int bb,
    uint32_t smb, int tid)
{
    const __nv_bfloat16* src = Wb + (size_t)(ni * 256) * 512 + kc * 64;
    uint32_t dst = smb + B_OFF + bb * B_BUF_B;
    #pragma unroll
    for (int it = 0; it < 8; it++) {
        int idx = tid + it * 256;
        int row = idx >> 3, ch = idx & 7;
        cpa16(dst + row * 144 + ch * 16, src + (size_t)row * 512 + ch * 8);
    }
    cpa_commit();
}

__device__ __forceinline__ void score_body(
    const float* __restrict__ Enc,
    const __nv_bfloat16* __restrict__ Wb,
    const float* __restrict__ addv, int a_stride,
    const float* __restrict__ vvec, int v_stride,
    float* __restrict__ score, int T, int bm)
{
    extern __shared__ char smc[];
    uint32_t smb = (uint32_t)__cvta_generic_to_shared(smc);
    float* smf = (float*)smc;
    int tid = threadIdx.x;
    int wid = tid >> 5, lane = tid & 31;
    int gr = lane >> 2, tg = lane & 3;
    int bA = bm / T;

    int m0 = (wid & 1) * 64;
    int n0 = (wid >> 1) * 64;

    b_prefetch(Wb, 0, 0, 0, smb, tid);
    b_prefetch(Wb, 0, 1, 1, smb, tid);

    for (int i = tid; i < 1024; i += 256) {
        int sl = i >> 9, n = i & 511;
        int bs = (bm + sl * 64) / T;
        smf[(SP_OFF >> 2) + i] = addv[(size_t)bs * a_stride + n];
        smf[(SV_OFF >> 2) + i] = vvec[(size_t)bs * v_stride + n];
    }

    for (int it = 0; it < 64; it++) {
        int idx = tid + it * 256;
        int row = idx >> 7, k = (idx & 127) << 2;
        float4 v = *(const float4*)(Enc + (size_t)(bm + row) * 512 + k);
        uint2 pk = make_uint2(pack_bf16(v.x, v.y), pack_bf16(v.z, v.w));
        *(uint2*)(smc + A_OFF + row * 1040 + k * 2) = pk;
    }
    __syncthreads();

    const uint32_t* Au = (const uint32_t*)(smc + A_OFF);
    float acc[4][8][4];

    for (int ph = 0; ph < 16; ph++) {
        int ni = ph >> 3, kc = ph & 7, bb = ph & 1;
        if (kc == 0) {
            #pragma unroll
            for (int mt = 0; mt < 4; mt++)
                #pragma unroll
                for (int nt = 0; nt < 8; nt++)
                    #pragma unroll
                    for (int q = 0; q < 4; q++) acc[mt][nt][q] = 0.f;
        }
        cpa_wait1();
        __syncthreads();

        const uint32_t* Bu = (const uint32_t*)(smc + B_OFF + bb * B_BUF_B);
        #pragma unroll
        for (int kk = 0; kk < 4; kk++) {
            int kw = kk * 8 + tg;
            uint32_t bf[8][2];
            #pragma unroll
            for (int nt = 0; nt < 8; nt++) {
                int bn = n0 + nt * 8 + gr;
                bf[nt][0] = Bu[bn * 36 + kw];
                bf[nt][1] = Bu[bn * 36 + kw + 4];
            }
            int aw = kc * 32 + kw;
            #pragma unroll
            for (int mt = 0; mt < 4; mt++) {
                int ar = m0 + mt * 16 + gr;
                uint32_t a0 = Au[ar * 260 + aw];
                uint32_t a1 = Au[(ar + 8) * 260 + aw];
                uint32_t a2 = Au[ar * 260 + aw + 4];
                uint32_t a3 = Au[(ar + 8) * 260 + aw + 4];
                #pragma unroll
                for (int nt = 0; nt < 8; nt++)
                    mma_bf16(acc[mt][nt], a0, a1, a2, a3, bf[nt][0], bf[nt][1]);
            }
        }
        __syncthreads();

        int ph2 = ph + 2;
        if (ph2 < 16)
            b_prefetch(Wb, ph2 >> 3, ph2 & 7, bb, smb, tid);
        else
            cpa_commit();

        if (kc == 7) {
            int slot = tg + 4 * (wid >> 1);
            int soff = ((bm + m0) / T - bA) * 512;
            const float* sp = smf + (SP_OFF >> 2) + soff;
            const float* sv = smf + (SV_OFF >> 2) + soff;
            float* red = smf + (RED_OFF >> 2);
            #pragma unroll
            for (int mt = 0; mt < 4; mt++) {
                int row = m0 + mt * 16 + gr;
                float p0 = 0.f, p1 = 0.f;
                #pragma unroll
                for (int nt = 0; nt < 8; nt++) {
                    int n = ni * 256 + n0 + nt * 8 + tg * 2;
                    float sp0 = sp[n], sp1 = sp[n + 1];
                    float sv0 = sv[n], sv1 = sv[n + 1];
                    p0 = fmaf(tanh_fast(sp0 + acc[mt][nt][0]), sv0, p0);
                    p0 = fmaf(tanh_fast(sp1 + acc[mt][nt][1]), sv1, p0);
                    p1 = fmaf(tanh_fast(sp0 + acc[mt][nt][2]), sv0, p1);
                    p1 = fmaf(tanh_fast(sp1 + acc[mt][nt][3]), sv1, p1);
                }
                if (ni == 0) {
                    red[row * 17 + slot] = p0;
                    red[(row + 8) * 17 + slot] = p1;
                } else {
                    red[row * 17 + slot] += p0;
                    red[(row + 8) * 17 + slot] += p1;
                }
            }
        }
    }
    __syncthreads();
    if (tid < 128) {
        float* red = smf + (RED_OFF >> 2);
        float s = 0.f;
        #pragma unroll
        for (int j = 0; j < 16; j++) s += red[tid * 17 + j];
        score[bm + tid] = s;
    }
}

__global__ __launch_bounds__(256, 1) void score_attn_kernel(
    const float* __restrict__ usdx, const float* __restrict__ bspn,
    const float* __restrict__ pv, const float* __restrict__ vw)
{
    int bx = blockIdx.x;
    const float* enc; float* out; int T, bm;
    if (bx < 256)      { enc = usdx; out = g_score_u; T = TU; bm = bx * 128; }
    else if (bx < 384) { enc = bspn; out = g_score_b; T = TB; bm = (bx - 256) * 128; }
    else               { enc = pv;   out = g_score_p; T = TP; bm = (bx - 384) * 128; }
    score_body(enc, g_wsc[0], g_p, 512, vw, 0, out, T, bm);
}

__global__ __launch_bounds__(256, 1) void score_cp_kernel(
    const float* __restrict__ bspn, const float* __restrict__ wcb)
{
    score_body(bspn, g_wsc[1], wcb, 0, g_hnew, 512, g_cpraw, TB, blockIdx.x * 128);
}

// =====================================================================
// In-place masked softmax over scores. grid = 384.
// =====================================================================
__global__ __launch_bounds__(256) void attw_kernel(
    const int* __restrict__ usdx_ids, const int* __restrict__ bspn_ids,
    const int* __restrict__ pv_ids)
{
    int bx = blockIdx.x;
    float* score; const int* ids; int T, b;
    if (bx < 128)      { score = g_score_u; ids = usdx_ids; T = TU; b = bx; }
    else if (bx < 256) { score = g_score_b; ids = bspn_ids; T = TB; b = bx - 128; }
    else               { score = g_score_p; ids = pv_ids;   T = TP; b = bx - 256; }

    int tid = threadIdx.x;
    __shared__ float sa[256];
    __shared__ float rbuf[256];

    float v = -INFINITY;
    if (tid < T) {
        float s = score[b * T + tid];
        if (ids[b * T + tid] == 0) s = NEGV;
        sa[tid] = s;
        v = s;
    }
    rbuf[tid] = v;
    __syncthreads();
    for (int s = 128; s > 0; s >>= 1) {
        if (tid < s) rbuf[tid] = fmaxf(rbuf[tid], rbuf[tid + s]);
        __syncthreads();
    }
    float mx = rbuf[0];
    __syncthreads();
    float e = 0.f;
    if (tid < T) e = expf(sa[tid] - mx);
    rbuf[tid] = e;
    __syncthreads();
    for (int s = 128; s > 0; s >>= 1) {
        if (tid < s) rbuf[tid] += rbuf[tid + s];
        __syncthreads();
    }
    float inv = 1.0f / rbuf[0];
    if (tid < T) score[b * T + tid] = e * inv;
}

// =====================================================================
// Context: ctx[b,h] = sum_t a[b,t] * enc[b,t,h].  grid = 1536, 128 thr.
// =====================================================================
__global__ __launch_bounds__(128) void ctx_kernel(
    const float* __restrict__ usdx, const float* __restrict__ bspn,
    const float* __restrict__ pv)
{
    int bx = blockIdx.x;
    const float* aw; const float* enc; float* ctx; int T, r;
    if (bx < 512)       { aw = g_score_u; enc = usdx; ctx = g_ctx_u; T = TU; r = bx; }
    else if (bx < 1024) { aw = g_score_b; enc = bspn; ctx = g_ctx_b; T = TB; r = bx - 512; }
    else                { aw = g_score_p; enc = pv;   ctx = g_ctx_p; T = TP; r = bx - 1024; }
    int b = r >> 2, hc = r & 3;
    int tid = threadIdx.x;

    __shared__ float sa[256];
    for (int i = tid; i < T; i += 128) sa[i] = aw[b * T + i];
    __syncthreads();

    const float* ep = enc + (size_t)b * T * 512 + hc * 128 + tid;
    float a0 = 0.f, a1 = 0.f, a2 = 0.f, a3 = 0.f;
    for (int t = 0; t < T; t += 4) {
        a0 = fmaf(sa[t],     ep[(size_t)t * 512],       a0);
        a1 = fmaf(sa[t + 1], ep[(size_t)(t + 1) * 512], a1);
        a2 = fmaf(sa[t + 2], ep[(size_t)(t + 2) * 512], a2);
        a3 = fmaf(sa[t + 3], ep[(size_t)(t + 3) * 512], a3);
    }
    ctx[b * 512 + hc * 128 + tid] = (a0 + a1) + (a2 + a3);
}

// =====================================================================
// Assemble GRU input directly in bf16: x = [emb|ctx_u|ctx_b|ctx_p|db|0pad]
// =====================================================================
__global__ void assemble_x_kernel(
    const int* __restrict__ w, const float* __restrict__ emb_table,
    const float* __restrict__ db)
{
    int idx = blockIdx.x * blockDim.x + threadIdx.x;
    if (idx >= BB * XDP) return;
    int b = idx / XDP, c = idx % XDP;
    float v;
    if (c < 512)       v = emb_table[(size_t)w[b] * 512 + c];
    else if (c < 1024) v = g_ctx_u[b * HD + c - 512];
    else if (c < 1536) v = g_ctx_b[b * HD + c - 1024];
    else if (c < 2048) v = g_ctx_p[b * HD + c - 1536];
    else if (c < 2080) v = db[b * PTRD + (c - 2048)];
    else               v = 0.f;
    g_xb[idx] = __float2bfloat16(v);
}

// =====================================================================
// GRU gate combine; writes hnew f32 + bf16.
// =====================================================================
__global__ void gru_gate_kernel(const float* __restrict__ h0)
{
    int idx = blockIdx.x * blockDim.x + threadIdx.x;
    if (idx >= BB * HD) return;
    int b = idx / HD, i = idx % HD;
    const float* gi = g_gi + (size_t)b * G3;
    const float* gh = g_gh + (size_t)b * G3;
    float r = 1.f / (1.f + expf(-(gi[i] + gh[i])));
    float z = 1.f / (1.f + expf(-(gi[512 + i] + gh[512 + i])));
    float n = tanhf(gi[1024 + i] + r * gh[1024 + i]);
    float hv = (1.f - z) * n + z * h0[idx];
    g_hnew[idx] = hv;
    g_hnb[idx] = __float2bfloat16(hv);
}

// =====================================================================
// Final: scatter cps, log-softmax over [gen | cps], merge + OOV.
// =====================================================================
__global__ __launch_bounds__(256) void final_kernel(
    const int* __restrict__ bspn_ids, const int* __restrict__ nounk,
    float* __restrict__ out)
{
    int b = blockIdx.x;
    int tid = threadIdx.x;
    __shared__ float s_cps[VD + TB];
    __shared__ float s_cpm[TB];
    __shared__ int   s_nk[TB];
    __shared__ float rbuf[256];

    for (int i = tid; i < VD + TB; i += 256) s_cps[i] = 0.f;
    if (tid < TB) {
        float c = g_cpraw[b * TB + tid];
        if (bspn_ids[b * TB + tid] == 0) c = NEGV;
        s_cpm[tid] = c;
        s_nk[tid] = nounk[b * TB + tid];
    }
    __syncthreads();
    if (tid == 0) {
        for (int j = 0; j < TB; j++) {
            int nk = s_nk[j];
            float c = s_cpm[j];
            if (nk < VD) s_cps[nk] += c;
            else         s_cps[VD + j] = c;
        }
    }
    __syncthreads();

    const float* genb = g_gen + (size_t)b * VD;
    float mx = -INFINITY;
    for (int i = tid; i < VD; i += 256) mx = fmaxf(mx, genb[i]);
    for (int i = tid; i < VD + TB; i += 256) mx = fmaxf(mx, s_cps[i]);
    rbuf[tid] = mx;
    __syncthreads();
    for (int s = 128; s > 0; s >>= 1) {
        if (tid < s) rbuf[tid] = fmaxf(rbuf[tid], rbuf[tid + s]);
        __syncthreads();
    }
    mx = rbuf[0];
    __syncthreads();
    float sm = 0.f;
    for (int i = tid; i < VD; i += 256) sm += expf(genb[i] - mx);
    for (int i = tid; i < VD + TB; i += 256) sm += expf(s_cps[i] - mx);
    rbuf[tid] = sm;
    __syncthreads();
    for (int s = 128; s > 0; s >>= 1) {
        if (tid < s) rbuf[tid] += rbuf[tid + s];
        __syncthreads();
    }
    float lse = mx + logf(rbuf[0]);
    __syncthreads();

    float* outb = out + (size_t)b * VOOVD;
    for (int n = tid; n < VD; n += 256) {
        float a = genb[n], c = s_cps[n];
        float m2 = fmaxf(a, c);
        outb[n] = m2 + logf(expf(a - m2) + expf(c - m2)) - lse;
    }
    for (int k = tid; k < VOOVD - VD; k += 256) {
        float add = 0.f;
        int target = VD + k;
        for (int j = 0; j < TB; j++)
            if (s_nk[j] == target) add += expf(s_cpm[j] - lse);
        outb[VD + k] = (add > 0.f) ? logf(add) : NEGV;
    }
}

// =====================================================================
// Host launcher
// =====================================================================
extern "C" void kernel_launch(void* const* d_in, const int* in_sizes, int n_in,
                              void* d_out, int out_size)
{
    const int*   dec_last_w = (const int*)  d_in[0];
    const float* h0         = (const float*)d_in[1];
    const float* usdx_h     = (const float*)d_in[2];
    const float* bspn_h     = (const float*)d_in[3];
    const float* pvaspn_h   = (const float*)d_in[4];
    const float* db         = (const float*)d_in[5];
    const int*   usdx_ids   = (const int*)  d_in[6];
    const int*   bspn_ids   = (const int*)  d_in[7];
    const int*   pvaspn_ids = (const int*)  d_in[8];
    const int*   bspn_nounk = (const int*)  d_in[9];
    const float* emb_table  = (const float*)d_in[11];
    const float* attn_W     = (const float*)d_in[12];
    const float* attn_b     = (const float*)d_in[13];
    const float* v_w        = (const float*)d_in[14];
    const float* Wcopy_w    = (const float*)d_in[15];
    const float* Wcopy_b    = (const float*)d_in[16];
    const float* Wgen_w     = (const float*)d_in[17];
    const float* Wgen_b     = (const float*)d_in[18];
    const float* gru_W_ih   = (const float*)d_in[19];
    const float* gru_W_hh   = (const float*)d_in[20];
    const float* gru_b_ih   = (const float*)d_in[21];
    const float* gru_b_hh   = (const float*)d_in[22];
    float* out = (float*)d_out;

    cudaFuncSetAttribute(score_attn_kernel,
                         cudaFuncAttributeMaxDynamicSharedMemorySize, SMEM_SZ);
    cudaFuncSetAttribute(score_cp_kernel,
                         cudaFuncAttributeMaxDynamicSharedMemorySize, SMEM_SZ);
    cudaFuncSetAttribute(mma_p_kernel,
                         cudaFuncAttributeMaxDynamicSharedMemorySize, GM_SMEM);
    cudaFuncSetAttribute(mma_gru_kernel,
                         cudaFuncAttributeMaxDynamicSharedMemorySize, GM_SMEM);
    cudaFuncSetAttribute(mma_gen_kernel,
                         cudaFuncAttributeMaxDynamicSharedMemorySize, GM_SMEM);

    // 0) stage all bf16 operands
    stage_all_kernel<<<(SO7 + 255) / 256, 256>>>(
        attn_W, Wcopy_w, gru_W_ih, gru_W_hh, Wgen_w, h0);

    // 1) p = h0 @ W1^T + attn_b  (bf16 mma)
    mma_p_kernel<<<4, 256, GM_SMEM>>>(attn_b);

    // 2) all three attention scores, one tensor-core launch
    score_attn_kernel<<<448, 256, SMEM_SZ>>>(usdx_h, bspn_h, pvaspn_h, v_w);

    // 3) masked softmax (in place) then parallel context
    attw_kernel<<<384, 256>>>(usdx_ids, bspn_ids, pvaspn_ids);
    ctx_kernel<<<1536, 128>>>(usdx_h, bspn_h, pvaspn_h);

    // 4) GRU: assemble x (bf16), gi+gh fused mma, gate
    assemble_x_kernel<<<(BB * XDP + 255) / 256, 256>>>(dec_last_w, emb_table, db);
    mma_gru_kernel<<<24, 256, GM_SMEM>>>(gru_b_ih, gru_b_hh);
    gru_gate_kernel<<<(BB * HD + 255) / 256, 256>>>(h0);

    // 5) gen logits (bf16 mma)
    mma_gen_kernel<<<24, 256, GM_SMEM>>>(Wgen_b);

    // 6) cp_raw on tensor cores
    score_cp_kernel<<<BB * TB / 128, 256, SMEM_SZ>>>(bspn_h, Wcopy_b);

    // 7) final scatter + log-softmax + merge
    final_kernel<<<BB, 256>>>(bspn_ids, bspn_nounk, out);
}